// round 1
// baseline (speedup 1.0000x reference)
#include <cuda_runtime.h>
#include <cuda_bf16.h>
#include <math.h>

// Problem constants
#define B   8
#define HD  768
#define LP  512
#define LL  256
#define CB  4096
#define NS  9
#define TT  4

// Output layout (concatenated flattened outputs, float32)
#define OFF_SUM 0                         // (8,4,768)
#define OFF_SL  24576                     // (8,4)
#define OFF_SP  24608                     // (8,4)
#define OFF_OP  24640                     // (8,4,4096)
#define OFF_CL  155712                    // (8,)

// ---------------- scratch (no allocations allowed) ----------------
__device__ float g_cat[B * 2 * HD];
__device__ float g_state[B * HD];
__device__ float g_stateq[B * HD];
__device__ float g_qprime[B * HD];
__device__ float g_u[B * HD];
__device__ float g_ctx[B * HD];
__device__ float g_oppre[B * HD];
__device__ float g_seed[B * NS * HD];
__device__ float g_slotq[B * NS * HD];
__device__ float g_slotqp[B * NS * HD];
__device__ float g_slotu[B * NS * HD];
__device__ float g_slotctx[B * NS * HD];
__device__ float g_scores[B * NS * LP];
__device__ float g_probs[B * NS];
__device__ float g_msum[B * HD];
__device__ float g_gi[B * 3 * HD];
__device__ float g_gh[B * 3 * HD];
__device__ unsigned long long g_amin[B];

// ---------------- kernels ----------------

// means of prompt / logic -> concatenated summary vector
__global__ void means_kernel(const float* __restrict__ prompt,
                             const float* __restrict__ logic,
                             float* __restrict__ cat) {
    int b = blockIdx.x;
    int h = blockIdx.y * 128 + threadIdx.x;
    const float* p = prompt + (size_t)b * LP * HD + h;
    float s0 = 0.f, s1 = 0.f;
    for (int l = 0; l < LP; l += 2) { s0 += p[l * HD]; s1 += p[(l + 1) * HD]; }
    cat[b * 2 * HD + h] = (s0 + s1) * (1.f / (float)LP);
    const float* g = logic + (size_t)b * LL * HD + h;
    s0 = 0.f; s1 = 0.f;
    for (int l = 0; l < LL; l += 2) { s0 += g[l * HD]; s1 += g[(l + 1) * HD]; }
    cat[b * 2 * HD + HD + h] = (s0 + s1) * (1.f / (float)LL);
}

// Y[M][N] = act(X[M][K] @ W[K][N]); W column access (W[k*N+n]); M tiled by 8
__global__ void gemv_col_kernel(const float* __restrict__ X,
                                const float* __restrict__ W,
                                float* __restrict__ Y,
                                int M, int K, int N, int act) {
    __shared__ float xs[8][256];
    int j = blockIdx.x * 128 + threadIdx.x;
    int m0 = blockIdx.y * 8;
    float acc[8];
#pragma unroll
    for (int m = 0; m < 8; m++) acc[m] = 0.f;
    for (int k0 = 0; k0 < K; k0 += 256) {
        int kc = K - k0; if (kc > 256) kc = 256;
        __syncthreads();
        for (int idx = threadIdx.x; idx < 8 * kc; idx += 128) {
            int m = idx / kc, kk = idx - m * kc;
            xs[m][kk] = X[(size_t)(m0 + m) * K + k0 + kk];
        }
        __syncthreads();
        for (int kk = 0; kk < kc; kk++) {
            float w = W[(size_t)(k0 + kk) * N + j];
#pragma unroll
            for (int m = 0; m < 8; m++) acc[m] = fmaf(xs[m][kk], w, acc[m]);
        }
    }
#pragma unroll
    for (int m = 0; m < 8; m++) {
        float v = acc[m];
        if (act == 1) v = tanhf(v);
        Y[(size_t)(m0 + m) * N + j] = v;
    }
}

// Y[M][N] = X[M][K] @ W^T  (W[n*K+k], dot of W rows); warp per n, M tiled by 8
__global__ void gemv_row_kernel(const float* __restrict__ X,
                                const float* __restrict__ W,
                                float* __restrict__ Y,
                                int K, int N) {
    int n = blockIdx.x * 8 + (threadIdx.x >> 5);
    int m0 = blockIdx.y * 8;
    int lane = threadIdx.x & 31;
    if (n >= N) return;
    const float* wr = W + (size_t)n * K;
    float acc[8];
#pragma unroll
    for (int m = 0; m < 8; m++) acc[m] = 0.f;
    for (int k = lane; k < K; k += 32) {
        float v = wr[k];
#pragma unroll
        for (int m = 0; m < 8; m++) acc[m] = fmaf(X[(size_t)(m0 + m) * K + k], v, acc[m]);
    }
#pragma unroll
    for (int m = 0; m < 8; m++)
#pragma unroll
        for (int off = 16; off; off >>= 1) acc[m] += __shfl_down_sync(0xffffffffu, acc[m], off);
    if (lane == 0) {
#pragma unroll
        for (int m = 0; m < 8; m++) Y[(size_t)(m0 + m) * N + n] = acc[m];
    }
}

// scores[q][l] = (prompt[b][l] . qp[q]) / sqrt(H); grid (B, LP/64), block 256
template <int NQ>
__global__ void scores_kernel(const float* __restrict__ qp,
                              const float* __restrict__ prompt,
                              float* __restrict__ scores) {
    __shared__ float sq[NQ * HD];
    int b = blockIdx.x;
    int l0 = blockIdx.y * 64;
    int tid = threadIdx.x, warp = tid >> 5, lane = tid & 31;
    for (int i = tid; i < NQ * HD; i += 256) sq[i] = qp[(size_t)b * NQ * HD + i];
    __syncthreads();
    const float* pr = prompt + ((size_t)b * LP + l0) * HD;
    const float scale = 1.0f / sqrtf((float)HD);
    for (int li = warp; li < 64; li += 8) {
        const float* row = pr + (size_t)li * HD;
        float acc[NQ];
#pragma unroll
        for (int s = 0; s < NQ; s++) acc[s] = 0.f;
        for (int k = lane; k < HD; k += 32) {
            float v = row[k];
#pragma unroll
            for (int s = 0; s < NQ; s++) acc[s] = fmaf(v, sq[s * HD + k], acc[s]);
        }
#pragma unroll
        for (int s = 0; s < NQ; s++)
#pragma unroll
            for (int off = 16; off; off >>= 1) acc[s] += __shfl_down_sync(0xffffffffu, acc[s], off);
        if (lane == 0) {
#pragma unroll
            for (int s = 0; s < NQ; s++) scores[(size_t)(b * NQ + s) * LP + l0 + li] = acc[s] * scale;
        }
    }
}

// in-place softmax over 512, one block of 256 per row
__global__ void softmax_kernel(float* __restrict__ sc) {
    float* row = sc + (size_t)blockIdx.x * LP;
    int tid = threadIdx.x;
    __shared__ float redm[8], reds[8];
    float v0 = row[tid], v1 = row[tid + 256];
    float mx = fmaxf(v0, v1);
#pragma unroll
    for (int off = 16; off; off >>= 1) mx = fmaxf(mx, __shfl_xor_sync(0xffffffffu, mx, off));
    if ((tid & 31) == 0) redm[tid >> 5] = mx;
    __syncthreads();
    mx = redm[0];
#pragma unroll
    for (int w = 1; w < 8; w++) mx = fmaxf(mx, redm[w]);
    float e0 = expf(v0 - mx), e1 = expf(v1 - mx);
    float s = e0 + e1;
#pragma unroll
    for (int off = 16; off; off >>= 1) s += __shfl_xor_sync(0xffffffffu, s, off);
    if ((tid & 31) == 0) reds[tid >> 5] = s;
    __syncthreads();
    float tot = 0.f;
#pragma unroll
    for (int w = 0; w < 8; w++) tot += reds[w];
    float inv = 1.f / tot;
    row[tid] = e0 * inv;
    row[tid + 256] = e1 * inv;
}

// u[q][j] = sum_l w[q][l] * prompt[b][l][j]; grid (B, HD/128), block 128
template <int NQ>
__global__ void usum_kernel(const float* __restrict__ w,
                            const float* __restrict__ prompt,
                            float* __restrict__ u_out) {
    __shared__ float sw[NQ * LP];
    int b = blockIdx.x;
    int j = blockIdx.y * 128 + threadIdx.x;
    for (int i = threadIdx.x; i < NQ * LP; i += 128) sw[i] = w[(size_t)b * NQ * LP + i];
    __syncthreads();
    const float* pr = prompt + (size_t)b * LP * HD;
    float acc[NQ];
#pragma unroll
    for (int s = 0; s < NQ; s++) acc[s] = 0.f;
#pragma unroll 8
    for (int l = 0; l < LP; l++) {
        float p = pr[(size_t)l * HD + j];
#pragma unroll
        for (int s = 0; s < NQ; s++) acc[s] = fmaf(sw[s * LP + l], p, acc[s]);
    }
#pragma unroll
    for (int s = 0; s < NQ; s++) u_out[(size_t)(b * NQ + s) * HD + j] = acc[s];
}

// slot_seed = ctx + slot_queries; gate prob = sigmoid(seed . w_gate + b_gate); resets argmin
__global__ void seed_gate_kernel(const float* __restrict__ ctx,
                                 const float* __restrict__ sq,
                                 const float* __restrict__ w_gate,
                                 const float* __restrict__ b_gate,
                                 float* __restrict__ seed,
                                 float* __restrict__ probs,
                                 unsigned long long* __restrict__ amin) {
    int q = blockIdx.x, b = q / NS, s = q - b * NS, tid = threadIdx.x;
    if (q == 0 && tid < B) amin[tid] = 0xFFFFFFFFFFFFFFFFull;
    float part = 0.f;
    for (int j = tid; j < HD; j += 256) {
        float v = ctx[b * HD + j] + sq[s * HD + j];
        seed[(size_t)q * HD + j] = v;
        part = fmaf(v, w_gate[j], part);
    }
#pragma unroll
    for (int off = 16; off; off >>= 1) part += __shfl_xor_sync(0xffffffffu, part, off);
    __shared__ float red[8];
    if ((tid & 31) == 0) red[tid >> 5] = part;
    __syncthreads();
    if (tid == 0) {
        float tot = 0.f;
#pragma unroll
        for (int w = 0; w < 8; w++) tot += red[w];
        float logit = tot + b_gate[0];
        probs[q] = 1.f / (1.f + expf(-logit));
    }
}

// distances to codebook; write op_logits, atomicMin packed (dist,idx)
__global__ void codebook_kernel(const float* __restrict__ oppre,
                                const float* __restrict__ cbk,
                                float* __restrict__ out_op,
                                unsigned long long* __restrict__ amin,
                                int step) {
    __shared__ float sp[B * HD];
    int tid = threadIdx.x;
    for (int i = tid; i < B * HD; i += 256) sp[i] = oppre[i];
    __syncthreads();
    int warp = tid >> 5, lane = tid & 31;
    int c = blockIdx.x * 8 + warp;
    const float* row = cbk + (size_t)c * HD;
    float acc[B];
#pragma unroll
    for (int b = 0; b < B; b++) acc[b] = 0.f;
    for (int k = lane; k < HD; k += 32) {
        float v = row[k];
#pragma unroll
        for (int b = 0; b < B; b++) { float d = sp[b * HD + k] - v; acc[b] = fmaf(d, d, acc[b]); }
    }
#pragma unroll
    for (int b = 0; b < B; b++)
#pragma unroll
        for (int off = 16; off; off >>= 1) acc[b] += __shfl_down_sync(0xffffffffu, acc[b], off);
    if (lane == 0) {
#pragma unroll
        for (int b = 0; b < B; b++) {
            out_op[OFF_OP + ((size_t)b * TT + step) * CB + c] = -acc[b];
            unsigned long long key = ((unsigned long long)__float_as_uint(acc[b]) << 32) | (unsigned)c;
            atomicMin(&amin[b], key);
        }
    }
}

// mask logic + slot summary + matrix summary + stop logit; writes outputs
__global__ void summary_kernel(const float* __restrict__ ctx,
                               const float* __restrict__ slotctx,
                               const float* __restrict__ probs,
                               const unsigned long long* __restrict__ amin,
                               const float* __restrict__ cbk,
                               const float* __restrict__ w_stop,
                               const float* __restrict__ b_stop,
                               float* __restrict__ msum,
                               float* __restrict__ out, int step) {
    __shared__ float maskf[NS];
    __shared__ float sdenom;
    __shared__ float red2[8];
    int b = blockIdx.x, tid = threadIdx.x;
    if (tid == 0) {
        bool anyg = false;
        for (int i = 0; i < B * NS; i++) if (probs[i] >= 0.5f) { anyg = true; break; }
        float cnt = 0.f;
        if (anyg) {
            for (int s = 0; s < NS; s++) {
                float m = (probs[b * NS + s] >= 0.5f) ? 1.f : 0.f;
                maskf[s] = m; cnt += m;
            }
        } else {
            int arg = 0; float best = probs[b * NS];
            for (int s = 1; s < NS; s++) if (probs[b * NS + s] > best) { best = probs[b * NS + s]; arg = s; }
            for (int s = 0; s < NS; s++) maskf[s] = (s == arg) ? 1.f : 0.f;
            cnt = 1.f;
        }
        sdenom = fmaxf(cnt, 1.f);
    }
    __syncthreads();
    int idx = (int)(amin[b] & 0xFFFFFFFFull);
    float inv = 1.f / sdenom;
    float spart = 0.f;
    for (int j = tid; j < HD; j += 256) {
        float ssum = 0.f;
#pragma unroll
        for (int s = 0; s < NS; s++) ssum += maskf[s] * slotctx[((size_t)b * NS + s) * HD + j];
        float ms = tanhf(cbk[(size_t)idx * HD + j] + ssum * inv);
        msum[b * HD + j] = ms;
        out[OFF_SUM + ((size_t)b * TT + step) * HD + j] = ms;
        spart = fmaf(ctx[b * HD + j], w_stop[j], spart);
        spart = fmaf(ms, w_stop[HD + j], spart);
    }
#pragma unroll
    for (int off = 16; off; off >>= 1) spart += __shfl_xor_sync(0xffffffffu, spart, off);
    if ((tid & 31) == 0) red2[tid >> 5] = spart;
    __syncthreads();
    if (tid == 0) {
        float tot = 0.f;
#pragma unroll
        for (int w = 0; w < 8; w++) tot += red2[w];
        float logit = tot + b_stop[0];
        out[OFF_SL + b * TT + step] = logit;
        out[OFF_SP + b * TT + step] = 1.f / (1.f + expf(-logit));
    }
}

// GRU input/hidden matvecs; grid (288,1,2) — z=0: gi from msum, z=1: gh from state
__global__ void gru_gemv_kernel(const float* __restrict__ msum,
                                const float* __restrict__ state,
                                const float* __restrict__ w_ih,
                                const float* __restrict__ w_hh,
                                float* __restrict__ gi,
                                float* __restrict__ gh) {
    const float* X = blockIdx.z ? state : msum;
    const float* W = blockIdx.z ? w_hh : w_ih;
    float* Y = blockIdx.z ? gh : gi;
    int n = blockIdx.x * 8 + (threadIdx.x >> 5);
    int lane = threadIdx.x & 31;
    if (n >= 3 * HD) return;
    const float* wr = W + (size_t)n * HD;
    float acc[B];
#pragma unroll
    for (int m = 0; m < B; m++) acc[m] = 0.f;
    for (int k = lane; k < HD; k += 32) {
        float v = wr[k];
#pragma unroll
        for (int m = 0; m < B; m++) acc[m] = fmaf(X[(size_t)m * HD + k], v, acc[m]);
    }
#pragma unroll
    for (int m = 0; m < B; m++)
#pragma unroll
        for (int off = 16; off; off >>= 1) acc[m] += __shfl_down_sync(0xffffffffu, acc[m], off);
    if (lane == 0) {
#pragma unroll
        for (int m = 0; m < B; m++) Y[(size_t)m * 3 * HD + n] = acc[m];
    }
}

__global__ void gru_combine_kernel(const float* __restrict__ gi,
                                   const float* __restrict__ gh,
                                   const float* __restrict__ b_ih,
                                   const float* __restrict__ b_hh,
                                   float* __restrict__ state) {
    int b = blockIdx.x, tid = threadIdx.x;
    for (int j = tid; j < HD; j += 256) {
        float ir = gi[b * 3 * HD + j] + b_ih[j];
        float iz = gi[b * 3 * HD + HD + j] + b_ih[HD + j];
        float inn = gi[b * 3 * HD + 2 * HD + j] + b_ih[2 * HD + j];
        float hr = gh[b * 3 * HD + j] + b_hh[j];
        float hz = gh[b * 3 * HD + HD + j] + b_hh[HD + j];
        float hn = gh[b * 3 * HD + 2 * HD + j] + b_hh[2 * HD + j];
        float r = 1.f / (1.f + expf(-(ir + hr)));
        float z = 1.f / (1.f + expf(-(iz + hz)));
        float n = tanhf(inn + r * hn);
        float h = state[b * HD + j];
        state[b * HD + j] = (1.f - z) * n + z * h;
    }
}

__global__ void chain_kernel(float* __restrict__ out) {
    int b = threadIdx.x;
    if (b < B) {
        int len = TT;
        for (int t = 0; t < TT; t++) {
            if (out[OFF_SL + b * TT + t] >= 0.f) { len = t + 1; break; }
        }
        out[OFF_CL + b] = (float)len;
    }
}

// ---------------- host ----------------
extern "C" void kernel_launch(void* const* d_in, const int* in_sizes, int n_in,
                              void* d_out, int out_size) {
    const float* logic    = (const float*)d_in[0];
    const float* prompt   = (const float*)d_in[1];
    const float* cbk      = (const float*)d_in[2];
    const float* w_init   = (const float*)d_in[3];
    const float* w_q      = (const float*)d_in[4];
    const float* w_k      = (const float*)d_in[5];
    const float* w_v      = (const float*)d_in[6];
    const float* slot_q_w = (const float*)d_in[7];   // slot_queries
    const float* w_slot_q = (const float*)d_in[8];
    const float* w_op_pre = (const float*)d_in[9];
    const float* w_gate   = (const float*)d_in[10];
    const float* b_gate   = (const float*)d_in[11];
    const float* w_stop   = (const float*)d_in[12];
    const float* b_stop   = (const float*)d_in[13];
    const float* w_ih     = (const float*)d_in[14];
    const float* w_hh     = (const float*)d_in[15];
    const float* b_ih     = (const float*)d_in[16];
    const float* b_hh     = (const float*)d_in[17];
    float* out = (float*)d_out;

    void *p_cat, *p_state, *p_stateq, *p_qprime, *p_u, *p_ctx, *p_oppre, *p_seed,
         *p_slotq, *p_slotqp, *p_slotu, *p_slotctx, *p_scores, *p_probs, *p_msum,
         *p_gi, *p_gh, *p_amin;
    cudaGetSymbolAddress(&p_cat, g_cat);
    cudaGetSymbolAddress(&p_state, g_state);
    cudaGetSymbolAddress(&p_stateq, g_stateq);
    cudaGetSymbolAddress(&p_qprime, g_qprime);
    cudaGetSymbolAddress(&p_u, g_u);
    cudaGetSymbolAddress(&p_ctx, g_ctx);
    cudaGetSymbolAddress(&p_oppre, g_oppre);
    cudaGetSymbolAddress(&p_seed, g_seed);
    cudaGetSymbolAddress(&p_slotq, g_slotq);
    cudaGetSymbolAddress(&p_slotqp, g_slotqp);
    cudaGetSymbolAddress(&p_slotu, g_slotu);
    cudaGetSymbolAddress(&p_slotctx, g_slotctx);
    cudaGetSymbolAddress(&p_scores, g_scores);
    cudaGetSymbolAddress(&p_probs, g_probs);
    cudaGetSymbolAddress(&p_msum, g_msum);
    cudaGetSymbolAddress(&p_gi, g_gi);
    cudaGetSymbolAddress(&p_gh, g_gh);
    cudaGetSymbolAddress(&p_amin, g_amin);

    float* cat    = (float*)p_cat;
    float* state  = (float*)p_state;
    float* stateq = (float*)p_stateq;
    float* qprime = (float*)p_qprime;
    float* u      = (float*)p_u;
    float* ctx    = (float*)p_ctx;
    float* oppre  = (float*)p_oppre;
    float* seed   = (float*)p_seed;
    float* slotq  = (float*)p_slotq;
    float* slotqp = (float*)p_slotqp;
    float* slotu  = (float*)p_slotu;
    float* slotctx= (float*)p_slotctx;
    float* scores = (float*)p_scores;
    float* probs  = (float*)p_probs;
    float* msum   = (float*)p_msum;
    float* gi     = (float*)p_gi;
    float* gh     = (float*)p_gh;
    unsigned long long* amin = (unsigned long long*)p_amin;

    // ---- precompute: summaries + initial state ----
    means_kernel<<<dim3(B, HD / 128), 128>>>(prompt, logic, cat);
    gemv_col_kernel<<<dim3(6, 1), 128>>>(cat, w_init, state, B, 2 * HD, HD, 1);

    for (int t = 0; t < TT; t++) {
        // state query path
        gemv_col_kernel<<<dim3(6, 1), 128>>>(state, w_q, stateq, B, HD, HD, 0);
        gemv_row_kernel<<<dim3(96, 1), 256>>>(stateq, w_k, qprime, HD, HD);
        scores_kernel<1><<<dim3(B, 8), 256>>>(qprime, prompt, scores);
        softmax_kernel<<<B, 256>>>(scores);
        usum_kernel<1><<<dim3(B, 6), 128>>>(scores, prompt, u);
        gemv_col_kernel<<<dim3(6, 1), 128>>>(u, w_v, ctx, B, HD, HD, 0);

        // slot seeds + gate probs (also resets argmin)
        seed_gate_kernel<<<B * NS, 256>>>(ctx, slot_q_w, w_gate, b_gate, seed, probs, amin);

        // op codebook path
        gemv_col_kernel<<<dim3(6, 1), 128>>>(ctx, w_op_pre, oppre, B, HD, HD, 0);
        codebook_kernel<<<CB / 8, 256>>>(oppre, cbk, out, amin, t);

        // slot attention path
        gemv_col_kernel<<<dim3(6, 9), 128>>>(seed, w_slot_q, slotq, B * NS, HD, HD, 0);
        gemv_row_kernel<<<dim3(96, 9), 256>>>(slotq, w_k, slotqp, HD, HD);
        scores_kernel<NS><<<dim3(B, 8), 256>>>(slotqp, prompt, scores);
        softmax_kernel<<<B * NS, 256>>>(scores);
        usum_kernel<NS><<<dim3(B, 6), 128>>>(scores, prompt, slotu);
        gemv_col_kernel<<<dim3(6, 9), 128>>>(slotu, w_v, slotctx, B * NS, HD, HD, 0);

        // summary + stop
        summary_kernel<<<B, 256>>>(ctx, slotctx, probs, amin, cbk, w_stop, b_stop,
                                   msum, out, t);

        // GRU state update
        gru_gemv_kernel<<<dim3(288, 1, 2), 256>>>(msum, state, w_ih, w_hh, gi, gh);
        gru_combine_kernel<<<B, 256>>>(gi, gh, b_ih, b_hh, state);
    }

    chain_kernel<<<1, 32>>>(out);
}

// round 2
// speedup vs baseline: 1.2555x; 1.2555x over previous
#include <cuda_runtime.h>
#include <math.h>

#define B   8
#define HD  768
#define LP  512
#define LL  256
#define CBN 4096
#define NS  9
#define TT  4

#define OFF_SUM 0
#define OFF_SL  24576
#define OFF_SP  24608
#define OFF_OP  24640
#define OFF_CL  155712

// ---------------- scratch ----------------
__device__ float g_cat[B * 2 * HD];
__device__ float g_state[B * HD];
__device__ float g_Wqk[HD * HD];
__device__ float g_Wsk[HD * HD];
__device__ float g_Wvop[HD * HD];
__device__ float g_sqk[NS * HD];
__device__ float g_gq[NS];
__device__ float g_qprime[B * HD];
__device__ float g_rawsc[B * NS * LP];
__device__ float g_u[B * HD];
__device__ float g_cxop[B * 2 * HD];       // [:,0:768]=ctx, [:,768:1536]=oppre
__device__ float g_ctxk[B * HD];
__device__ float g_wcomb[B * LP];
__device__ float g_uslot[B * HD];
__device__ float g_msum[B * HD];
__device__ float g_gi[B * 3 * HD];
__device__ float g_gh[B * 3 * HD];
__device__ float g_stoplog[B];
__device__ unsigned long long g_amin[B];

// ---------------- precompute kernels ----------------

__global__ void means_kernel(const float* __restrict__ prompt,
                             const float* __restrict__ logic,
                             float* __restrict__ cat) {
    int b = blockIdx.x;
    int h = blockIdx.y * 128 + threadIdx.x;
    const float* p = prompt + (size_t)b * LP * HD + h;
    float s0 = 0.f, s1 = 0.f;
    for (int l = 0; l < LP; l += 2) { s0 += p[l * HD]; s1 += p[(l + 1) * HD]; }
    cat[b * 2 * HD + h] = (s0 + s1) * (1.f / (float)LP);
    const float* g = logic + (size_t)b * LL * HD + h;
    s0 = 0.f; s1 = 0.f;
    for (int l = 0; l < LL; l += 2) { s0 += g[l * HD]; s1 += g[(l + 1) * HD]; }
    cat[b * 2 * HD + HD + h] = (s0 + s1) * (1.f / (float)LL);
}

// C[M,N] = A[M,K] * B[N,K]^T  (768^3), 64x64 tile, 256 thr, 4x4 micro
__global__ void gemm_abt(const float* __restrict__ A, const float* __restrict__ Bm,
                         float* __restrict__ C) {
    __shared__ float As[64][17];
    __shared__ float Bs[64][17];
    int bx = blockIdx.x * 64, by = blockIdx.y * 64;
    int tid = threadIdx.x;
    int tx = tid & 15, ty = tid >> 4;
    float acc[4][4] = {};
    for (int kt = 0; kt < HD; kt += 16) {
        __syncthreads();
        for (int idx = tid; idx < 64 * 16; idx += 256) {
            int r = idx >> 4, c = idx & 15;
            As[r][c] = A[(size_t)(by + r) * HD + kt + c];
            Bs[r][c] = Bm[(size_t)(bx + r) * HD + kt + c];
        }
        __syncthreads();
#pragma unroll
        for (int kk = 0; kk < 16; kk++) {
            float a[4], bb[4];
#pragma unroll
            for (int i = 0; i < 4; i++) a[i] = As[ty * 4 + i][kk];
#pragma unroll
            for (int j = 0; j < 4; j++) bb[j] = Bs[tx * 4 + j][kk];
#pragma unroll
            for (int i = 0; i < 4; i++)
#pragma unroll
                for (int j = 0; j < 4; j++) acc[i][j] = fmaf(a[i], bb[j], acc[i][j]);
        }
    }
    for (int i = 0; i < 4; i++)
        for (int j = 0; j < 4; j++)
            C[(size_t)(by + ty * 4 + i) * HD + bx + tx * 4 + j] = acc[i][j];
}

// C[M,N] = A[M,K] * B[K,N]
__global__ void gemm_ab(const float* __restrict__ A, const float* __restrict__ Bm,
                        float* __restrict__ C) {
    __shared__ float As[64][17];
    __shared__ float Bs[16][65];
    int bx = blockIdx.x * 64, by = blockIdx.y * 64;
    int tid = threadIdx.x;
    int tx = tid & 15, ty = tid >> 4;
    float acc[4][4] = {};
    for (int kt = 0; kt < HD; kt += 16) {
        __syncthreads();
        for (int idx = tid; idx < 64 * 16; idx += 256) {
            int r = idx >> 4, c = idx & 15;
            As[r][c] = A[(size_t)(by + r) * HD + kt + c];
            int r2 = idx >> 6, c2 = idx & 63;
            Bs[r2][c2] = Bm[(size_t)(kt + r2) * HD + bx + c2];
        }
        __syncthreads();
#pragma unroll
        for (int kk = 0; kk < 16; kk++) {
            float a[4], bb[4];
#pragma unroll
            for (int i = 0; i < 4; i++) a[i] = As[ty * 4 + i][kk];
#pragma unroll
            for (int j = 0; j < 4; j++) bb[j] = Bs[kk][tx * 4 + j];
#pragma unroll
            for (int i = 0; i < 4; i++)
#pragma unroll
                for (int j = 0; j < 4; j++) acc[i][j] = fmaf(a[i], bb[j], acc[i][j]);
        }
    }
    for (int i = 0; i < 4; i++)
        for (int j = 0; j < 4; j++)
            C[(size_t)(by + ty * 4 + i) * HD + bx + tx * 4 + j] = acc[i][j];
}

// zero scratch + slot-gate dots gq[s] = slot_queries[s] . w_gate
__global__ void init_kernel(const float* __restrict__ slotq,
                            const float* __restrict__ w_gate,
                            float* __restrict__ gq,
                            float* __restrict__ qprime, float* __restrict__ cxop,
                            float* __restrict__ ctxk, float* __restrict__ stoplog,
                            unsigned long long* __restrict__ amin) {
    int gid = blockIdx.x * 256 + threadIdx.x;
    if (gid < B * HD) qprime[gid] = 0.f;
    if (gid < B * 2 * HD) cxop[gid] = 0.f;
    if (gid < B * HD) ctxk[gid] = 0.f;
    if (gid < B) { stoplog[gid] = 0.f; amin[gid] = 0xFFFFFFFFFFFFFFFFull; }
    if (blockIdx.x == 0) {
        int warp = threadIdx.x >> 5, lane = threadIdx.x & 31;
        for (int s = warp; s < NS; s += 8) {
            float p = 0.f;
            for (int k = lane; k < HD; k += 32) p = fmaf(slotq[s * HD + k], w_gate[k], p);
#pragma unroll
            for (int off = 16; off; off >>= 1) p += __shfl_down_sync(0xffffffffu, p, off);
            if (lane == 0) gq[s] = p;
        }
    }
}

// ---------------- chain kernels ----------------

// Y[m][j] (+)= act(sum_k X[m][k] W[k][j]); grid (N/128, 1, SK), block 128
template <int TM, int ACT, int SK>
__global__ void gemv_col(const float* __restrict__ X, const float* __restrict__ W,
                         float* __restrict__ Y, int K, int N, int ldx, int ldy) {
    __shared__ float xs[TM][192];
    int j = blockIdx.x * 128 + threadIdx.x;
    int kbeg = blockIdx.z * (K / SK);
    int kend = kbeg + K / SK;
    float acc[TM];
#pragma unroll
    for (int m = 0; m < TM; m++) acc[m] = 0.f;
    for (int k0 = kbeg; k0 < kend; k0 += 192) {
        __syncthreads();
        for (int idx = threadIdx.x; idx < TM * 192; idx += 128) {
            int m = idx / 192, kk = idx - m * 192;
            xs[m][kk] = X[(size_t)m * ldx + k0 + kk];
        }
        __syncthreads();
#pragma unroll 4
        for (int kk = 0; kk < 192; kk++) {
            float w = W[(size_t)(k0 + kk) * N + j];
#pragma unroll
            for (int m = 0; m < TM; m++) acc[m] = fmaf(xs[m][kk], w, acc[m]);
        }
    }
#pragma unroll
    for (int m = 0; m < TM; m++) {
        float v = acc[m];
        if (ACT) v = tanhf(v);
        if (SK == 1) Y[(size_t)m * ldy + j] = v;
        else atomicAdd(&Y[(size_t)m * ldy + j], v);
    }
}

// Y[8][1536]: cols 0..767 via Wa (w_v), 768..1535 via Wb (Wvop); X = u[8][768]
__global__ void gemv_dual(const float* __restrict__ X, const float* __restrict__ Wa,
                          const float* __restrict__ Wb, float* __restrict__ Y) {
    __shared__ float xs[8][192];
    int j = blockIdx.x * 128 + threadIdx.x;
    const float* W = (j < HD) ? Wa : Wb;
    int col = (j < HD) ? j : j - HD;
    int kbeg = blockIdx.z * 192;
    float acc[8];
#pragma unroll
    for (int m = 0; m < 8; m++) acc[m] = 0.f;
    for (int idx = threadIdx.x; idx < 8 * 192; idx += 128) {
        int m = idx / 192, kk = idx - m * 192;
        xs[m][kk] = X[(size_t)m * HD + kbeg + kk];
    }
    __syncthreads();
#pragma unroll 4
    for (int kk = 0; kk < 192; kk++) {
        float w = W[(size_t)(kbeg + kk) * HD + col];
#pragma unroll
        for (int m = 0; m < 8; m++) acc[m] = fmaf(xs[m][kk], w, acc[m]);
    }
#pragma unroll
    for (int m = 0; m < 8; m++) atomicAdd(&Y[(size_t)m * 2 * HD + j], acc[m]);
}

// raw scaled scores; if ADDQ: query s = qp[b] + sqk[s]
template <int NQ, bool ADDQ>
__global__ void scores_kernel(const float* __restrict__ qp, const float* __restrict__ sqk,
                              const float* __restrict__ prompt, float* __restrict__ outs) {
    __shared__ float sq[NQ * HD];
    int b = blockIdx.x, l0 = blockIdx.y * 64;
    int tid = threadIdx.x, warp = tid >> 5, lane = tid & 31;
    for (int i = tid; i < NQ * HD; i += 256) {
        if (ADDQ) { int s = i / HD, k = i - s * HD; sq[i] = qp[b * HD + k] + sqk[i]; }
        else sq[i] = qp[(size_t)b * NQ * HD + i];
    }
    __syncthreads();
    const float scale = 0.03608439182435161f;  // 1/sqrt(768)
    const float* pr = prompt + ((size_t)b * LP + l0) * HD;
    for (int li = warp; li < 64; li += 8) {
        const float* row = pr + (size_t)li * HD;
        float acc[NQ];
#pragma unroll
        for (int s = 0; s < NQ; s++) acc[s] = 0.f;
#pragma unroll 2
        for (int k = lane; k < HD; k += 32) {
            float v = row[k];
#pragma unroll
            for (int s = 0; s < NQ; s++) acc[s] = fmaf(v, sq[s * HD + k], acc[s]);
        }
#pragma unroll
        for (int s = 0; s < NQ; s++)
#pragma unroll
            for (int off = 16; off; off >>= 1) acc[s] += __shfl_down_sync(0xffffffffu, acc[s], off);
        if (lane == 0) {
#pragma unroll
            for (int s = 0; s < NQ; s++)
                outs[(size_t)(b * NQ + s) * LP + l0 + li] = acc[s] * scale;
        }
    }
}

// u[b][j] = sum_l w[b][l] prompt[b][l][j]; if SM: softmax(w) inline. grid (B,6), 128 thr
template <bool SM>
__global__ void usum_kernel(const float* __restrict__ w, const float* __restrict__ prompt,
                            float* __restrict__ uo) {
    __shared__ float sw[LP];
    __shared__ float red[4];
    int b = blockIdx.x, tid = threadIdx.x, warp = tid >> 5, lane = tid & 31;
    int j = blockIdx.y * 128 + tid;
    for (int i = tid; i < LP; i += 128) sw[i] = w[b * LP + i];
    __syncthreads();
    float inv = 1.f;
    if (SM) {
        float mx = -1e30f;
        for (int i = tid; i < LP; i += 128) mx = fmaxf(mx, sw[i]);
#pragma unroll
        for (int off = 16; off; off >>= 1) mx = fmaxf(mx, __shfl_xor_sync(0xffffffffu, mx, off));
        if (lane == 0) red[warp] = mx;
        __syncthreads();
        mx = fmaxf(fmaxf(red[0], red[1]), fmaxf(red[2], red[3]));
        __syncthreads();
        float s = 0.f;
        for (int i = tid; i < LP; i += 128) {
            float e = expf(sw[i] - mx);
            sw[i] = e;
            s += e;
        }
#pragma unroll
        for (int off = 16; off; off >>= 1) s += __shfl_xor_sync(0xffffffffu, s, off);
        if (lane == 0) red[warp] = s;
        __syncthreads();
        inv = 1.f / (red[0] + red[1] + red[2] + red[3]);
    }
    __syncthreads();
    float acc = 0.f;
    const float* pr = prompt + (size_t)b * LP * HD + j;
#pragma unroll 8
    for (int l = 0; l < LP; l++) acc = fmaf(sw[l], pr[(size_t)l * HD], acc);
    uo[b * HD + j] = acc * inv;
}

// codebook distances; op_logits + packed argmin
__global__ void codebook_kernel(const float* __restrict__ cxop, const float* __restrict__ cbk,
                                float* __restrict__ out, unsigned long long* __restrict__ amin,
                                int step) {
    __shared__ float sp[B * HD];
    int tid = threadIdx.x;
    for (int i = tid; i < B * HD; i += 256) {
        int b = i / HD, k = i - b * HD;
        sp[i] = cxop[b * 2 * HD + HD + k];
    }
    __syncthreads();
    int warp = tid >> 5, lane = tid & 31;
    int c = blockIdx.x * 8 + warp;
    const float* row = cbk + (size_t)c * HD;
    float acc[B];
#pragma unroll
    for (int b = 0; b < B; b++) acc[b] = 0.f;
#pragma unroll 2
    for (int k = lane; k < HD; k += 32) {
        float v = row[k];
#pragma unroll
        for (int b = 0; b < B; b++) { float d = sp[b * HD + k] - v; acc[b] = fmaf(d, d, acc[b]); }
    }
#pragma unroll
    for (int b = 0; b < B; b++)
#pragma unroll
        for (int off = 16; off; off >>= 1) acc[b] += __shfl_down_sync(0xffffffffu, acc[b], off);
    if (lane == 0) {
#pragma unroll
        for (int b = 0; b < B; b++) {
            out[OFF_OP + ((size_t)b * TT + step) * CBN + c] = -acc[b];
            unsigned long long key = ((unsigned long long)__float_as_uint(acc[b]) << 32) | (unsigned)c;
            atomicMin(&amin[b], key);
        }
    }
}

// gates + mask + per-slot softmax collapsed into one combined weight vector
__global__ void collapse_kernel(const float* __restrict__ rawsc, const float* __restrict__ cxop,
                                const float* __restrict__ w_gate, const float* __restrict__ gq,
                                const float* __restrict__ b_gate, float* __restrict__ wcomb) {
    __shared__ float ssc[NS * LP];
    __shared__ float sgate[B];
    __shared__ float maskf[NS];
    __shared__ float sinvcnt;
    __shared__ float redm[8], reds[8];
    int b = blockIdx.x, tid = threadIdx.x, warp = tid >> 5, lane = tid & 31;
    for (int i = tid; i < NS * LP; i += 256) ssc[i] = rawsc[(size_t)b * NS * LP + i];
    {
        int bb = warp;  // 8 warps, one per batch row
        float p = 0.f;
        for (int k = lane; k < HD; k += 32) p = fmaf(cxop[bb * 2 * HD + k], w_gate[k], p);
#pragma unroll
        for (int off = 16; off; off >>= 1) p += __shfl_down_sync(0xffffffffu, p, off);
        if (lane == 0) sgate[bb] = p;
    }
    __syncthreads();
    if (tid == 0) {
        float bg = b_gate[0];
        bool any = false;
        for (int bb = 0; bb < B; bb++)
            for (int s = 0; s < NS; s++) {
                float pr = 1.f / (1.f + expf(-(sgate[bb] + gq[s] + bg)));
                if (pr >= 0.5f) any = true;
            }
        float cnt = 0.f;
        if (any) {
            for (int s = 0; s < NS; s++) {
                float pr = 1.f / (1.f + expf(-(sgate[b] + gq[s] + bg)));
                float m = (pr >= 0.5f) ? 1.f : 0.f;
                maskf[s] = m; cnt += m;
            }
        } else {
            int arg = 0; float best = 1.f / (1.f + expf(-(sgate[b] + gq[0] + bg)));
            for (int s = 1; s < NS; s++) {
                float pr = 1.f / (1.f + expf(-(sgate[b] + gq[s] + bg)));
                if (pr > best) { best = pr; arg = s; }
            }
            for (int s = 0; s < NS; s++) maskf[s] = (s == arg) ? 1.f : 0.f;
            cnt = 1.f;
        }
        sinvcnt = 1.f / fmaxf(cnt, 1.f);
    }
    __syncthreads();
    float wa0 = 0.f, wa1 = 0.f;
    for (int s = 0; s < NS; s++) {
        float v0 = ssc[s * LP + tid], v1 = ssc[s * LP + tid + 256];
        float mx = fmaxf(v0, v1);
#pragma unroll
        for (int off = 16; off; off >>= 1) mx = fmaxf(mx, __shfl_xor_sync(0xffffffffu, mx, off));
        if (lane == 0) redm[warp] = mx;
        __syncthreads();
        mx = redm[0];
#pragma unroll
        for (int w = 1; w < 8; w++) mx = fmaxf(mx, redm[w]);
        float e0 = expf(v0 - mx), e1 = expf(v1 - mx);
        float sm = e0 + e1;
#pragma unroll
        for (int off = 16; off; off >>= 1) sm += __shfl_xor_sync(0xffffffffu, sm, off);
        if (lane == 0) reds[warp] = sm;
        __syncthreads();
        float tot = 0.f;
#pragma unroll
        for (int w = 0; w < 8; w++) tot += reds[w];
        float f = maskf[s] * sinvcnt / tot;
        wa0 = fmaf(e0, f, wa0);
        wa1 = fmaf(e1, f, wa1);
        __syncthreads();
    }
    wcomb[b * LP + tid] = wa0;
    wcomb[b * LP + tid + 256] = wa1;
}

// slot_summary gemv + tanh(op_emb + .) + outputs + stop-logit partials
__global__ void summary_kernel(const float* __restrict__ uslot, const float* __restrict__ w_v,
                               const float* __restrict__ cxop,
                               const unsigned long long* __restrict__ amin,
                               const float* __restrict__ cbk, const float* __restrict__ w_stop,
                               float* __restrict__ msum, float* __restrict__ out,
                               float* __restrict__ stoplog, int step) {
    __shared__ float xs[8][192];
    __shared__ float red[4][8];
    int j = blockIdx.x * 128 + threadIdx.x;
    int tid = threadIdx.x, warp = tid >> 5, lane = tid & 31;
    float acc[8];
#pragma unroll
    for (int m = 0; m < 8; m++) acc[m] = 0.f;
    for (int k0 = 0; k0 < HD; k0 += 192) {
        __syncthreads();
        for (int idx = tid; idx < 8 * 192; idx += 128) {
            int m = idx / 192, kk = idx - m * 192;
            xs[m][kk] = uslot[m * HD + k0 + kk];
        }
        __syncthreads();
#pragma unroll 4
        for (int kk = 0; kk < 192; kk++) {
            float w = w_v[(size_t)(k0 + kk) * HD + j];
#pragma unroll
            for (int m = 0; m < 8; m++) acc[m] = fmaf(xs[m][kk], w, acc[m]);
        }
    }
    float ws0 = w_stop[j], ws1 = w_stop[HD + j];
    float sp[8];
#pragma unroll
    for (int m = 0; m < 8; m++) {
        int idx = (int)(amin[m] & 0xFFFFFFFFull);
        float ms = tanhf(cbk[(size_t)idx * HD + j] + acc[m]);
        msum[m * HD + j] = ms;
        out[OFF_SUM + ((size_t)m * TT + step) * HD + j] = ms;
        sp[m] = cxop[m * 2 * HD + j] * ws0 + ms * ws1;
    }
#pragma unroll
    for (int m = 0; m < 8; m++) {
        float v = sp[m];
#pragma unroll
        for (int off = 16; off; off >>= 1) v += __shfl_down_sync(0xffffffffu, v, off);
        if (lane == 0) red[warp][m] = v;
    }
    __syncthreads();
    if (tid < 8) {
        float t = red[0][tid] + red[1][tid] + red[2][tid] + red[3][tid];
        atomicAdd(&stoplog[tid], t);
    }
}

// GRU matvecs (z=0: gi from msum, z=1: gh from state); X staged to smem
__global__ void gru_gemv(const float* __restrict__ msum, const float* __restrict__ state,
                         const float* __restrict__ w_ih, const float* __restrict__ w_hh,
                         float* __restrict__ gi, float* __restrict__ gh) {
    __shared__ float xs[8 * HD];
    const float* X = blockIdx.z ? state : msum;
    const float* W = blockIdx.z ? w_hh : w_ih;
    float* Y = blockIdx.z ? gh : gi;
    int tid = threadIdx.x;
    for (int i = tid; i < 8 * HD; i += 256) xs[i] = X[i];
    __syncthreads();
    int n = blockIdx.x * 8 + (tid >> 5), lane = tid & 31;
    const float* wr = W + (size_t)n * HD;
    float acc[8];
#pragma unroll
    for (int m = 0; m < 8; m++) acc[m] = 0.f;
#pragma unroll 3
    for (int k = lane; k < HD; k += 32) {
        float v = wr[k];
#pragma unroll
        for (int m = 0; m < 8; m++) acc[m] = fmaf(xs[m * HD + k], v, acc[m]);
    }
#pragma unroll
    for (int m = 0; m < 8; m++)
#pragma unroll
        for (int off = 16; off; off >>= 1) acc[m] += __shfl_down_sync(0xffffffffu, acc[m], off);
    if (lane == 0) {
#pragma unroll
        for (int m = 0; m < 8; m++) Y[(size_t)m * 3 * HD + n] = acc[m];
    }
}

// GRU combine + SL/SP outputs + zero per-step atomic scratch for next step
__global__ void gru_combine(const float* __restrict__ gi, const float* __restrict__ gh,
                            const float* __restrict__ b_ih, const float* __restrict__ b_hh,
                            float* __restrict__ state, float* __restrict__ out,
                            const float* __restrict__ b_stop, float* __restrict__ stoplog,
                            unsigned long long* __restrict__ amin,
                            float* __restrict__ qprime, float* __restrict__ cxop,
                            float* __restrict__ ctxk, int step) {
    int b = blockIdx.x, tid = threadIdx.x;
    for (int j = tid; j < HD; j += 256) {
        float ir = gi[b * 3 * HD + j] + b_ih[j];
        float iz = gi[b * 3 * HD + HD + j] + b_ih[HD + j];
        float inn = gi[b * 3 * HD + 2 * HD + j] + b_ih[2 * HD + j];
        float hr = gh[b * 3 * HD + j] + b_hh[j];
        float hz = gh[b * 3 * HD + HD + j] + b_hh[HD + j];
        float hn = gh[b * 3 * HD + 2 * HD + j] + b_hh[2 * HD + j];
        float r = 1.f / (1.f + expf(-(ir + hr)));
        float z = 1.f / (1.f + expf(-(iz + hz)));
        float n = tanhf(inn + r * hn);
        float h = state[b * HD + j];
        state[b * HD + j] = (1.f - z) * n + z * h;
    }
    if (tid == 0) {
        float lg = stoplog[b] + b_stop[0];
        out[OFF_SL + b * TT + step] = lg;
        out[OFF_SP + b * TT + step] = 1.f / (1.f + expf(-lg));
        stoplog[b] = 0.f;
        amin[b] = 0xFFFFFFFFFFFFFFFFull;
    }
    for (int j = tid; j < HD; j += 256) { qprime[b * HD + j] = 0.f; ctxk[b * HD + j] = 0.f; }
    for (int j = tid; j < 2 * HD; j += 256) cxop[b * 2 * HD + j] = 0.f;
}

__global__ void chain_kernel(float* __restrict__ out) {
    int b = threadIdx.x;
    if (b < B) {
        int len = TT;
        for (int t = 0; t < TT; t++)
            if (out[OFF_SL + b * TT + t] >= 0.f) { len = t + 1; break; }
        out[OFF_CL + b] = (float)len;
    }
}

// ---------------- host ----------------
extern "C" void kernel_launch(void* const* d_in, const int* in_sizes, int n_in,
                              void* d_out, int out_size) {
    const float* logic    = (const float*)d_in[0];
    const float* prompt   = (const float*)d_in[1];
    const float* cbk      = (const float*)d_in[2];
    const float* w_init   = (const float*)d_in[3];
    const float* w_q      = (const float*)d_in[4];
    const float* w_k      = (const float*)d_in[5];
    const float* w_v      = (const float*)d_in[6];
    const float* slot_q   = (const float*)d_in[7];
    const float* w_slot_q = (const float*)d_in[8];
    const float* w_op_pre = (const float*)d_in[9];
    const float* w_gate   = (const float*)d_in[10];
    const float* b_gate   = (const float*)d_in[11];
    const float* w_stop   = (const float*)d_in[12];
    const float* b_stop   = (const float*)d_in[13];
    const float* w_ih     = (const float*)d_in[14];
    const float* w_hh     = (const float*)d_in[15];
    const float* b_ih     = (const float*)d_in[16];
    const float* b_hh     = (const float*)d_in[17];
    float* out = (float*)d_out;

    void *p;
    float *cat, *state, *Wqk, *Wsk, *Wvop, *sqk, *gq, *qprime, *rawsc, *u, *cxop,
          *ctxk, *wcomb, *uslot, *msum, *gi, *gh, *stoplog;
    unsigned long long* amin;
    cudaGetSymbolAddress(&p, g_cat);    cat = (float*)p;
    cudaGetSymbolAddress(&p, g_state);  state = (float*)p;
    cudaGetSymbolAddress(&p, g_Wqk);    Wqk = (float*)p;
    cudaGetSymbolAddress(&p, g_Wsk);    Wsk = (float*)p;
    cudaGetSymbolAddress(&p, g_Wvop);   Wvop = (float*)p;
    cudaGetSymbolAddress(&p, g_sqk);    sqk = (float*)p;
    cudaGetSymbolAddress(&p, g_gq);     gq = (float*)p;
    cudaGetSymbolAddress(&p, g_qprime); qprime = (float*)p;
    cudaGetSymbolAddress(&p, g_rawsc);  rawsc = (float*)p;
    cudaGetSymbolAddress(&p, g_u);      u = (float*)p;
    cudaGetSymbolAddress(&p, g_cxop);   cxop = (float*)p;
    cudaGetSymbolAddress(&p, g_ctxk);   ctxk = (float*)p;
    cudaGetSymbolAddress(&p, g_wcomb);  wcomb = (float*)p;
    cudaGetSymbolAddress(&p, g_uslot);  uslot = (float*)p;
    cudaGetSymbolAddress(&p, g_msum);   msum = (float*)p;
    cudaGetSymbolAddress(&p, g_gi);     gi = (float*)p;
    cudaGetSymbolAddress(&p, g_gh);     gh = (float*)p;
    cudaGetSymbolAddress(&p, g_stoplog);stoplog = (float*)p;
    cudaGetSymbolAddress(&p, g_amin);   amin = (unsigned long long*)p;

    // precompute
    means_kernel<<<dim3(B, 6), 128>>>(prompt, logic, cat);
    gemv_col<8, 1, 1><<<dim3(6, 1, 1), 128>>>(cat, w_init, state, 2 * HD, HD, 2 * HD, HD);
    gemm_abt<<<dim3(12, 12), 256>>>(w_q, w_k, Wqk);
    gemm_abt<<<dim3(12, 12), 256>>>(w_slot_q, w_k, Wsk);
    gemm_ab<<<dim3(12, 12), 256>>>(w_v, w_op_pre, Wvop);
    gemv_col<9, 0, 1><<<dim3(6, 1, 1), 128>>>(slot_q, Wsk, sqk, HD, HD, HD, HD);
    init_kernel<<<48, 256>>>(slot_q, w_gate, gq, qprime, cxop, ctxk, stoplog, amin);

    for (int t = 0; t < TT; t++) {
        gemv_col<8, 0, 4><<<dim3(6, 1, 4), 128>>>(state, Wqk, qprime, HD, HD, HD, HD);
        scores_kernel<1, false><<<dim3(B, 8), 256>>>(qprime, nullptr, prompt, rawsc);
        usum_kernel<true><<<dim3(B, 6), 128>>>(rawsc, prompt, u);
        gemv_dual<<<dim3(12, 1, 4), 128>>>(u, w_v, Wvop, cxop);
        codebook_kernel<<<512, 256>>>(cxop, cbk, out, amin, t);
        gemv_col<8, 0, 4><<<dim3(6, 1, 4), 128>>>(cxop, Wsk, ctxk, HD, HD, 2 * HD, HD);
        scores_kernel<NS, true><<<dim3(B, 8), 256>>>(ctxk, sqk, prompt, rawsc);
        collapse_kernel<<<B, 256>>>(rawsc, cxop, w_gate, gq, b_gate, wcomb);
        usum_kernel<false><<<dim3(B, 6), 128>>>(wcomb, prompt, uslot);
        summary_kernel<<<6, 128>>>(uslot, w_v, cxop, amin, cbk, w_stop, msum, out, stoplog, t);
        gru_gemv<<<dim3(288, 1, 2), 256>>>(msum, state, w_ih, w_hh, gi, gh);
        gru_combine<<<B, 256>>>(gi, gh, b_ih, b_hh, state, out, b_stop, stoplog, amin,
                                qprime, cxop, ctxk, t);
    }

    chain_kernel<<<1, 32>>>(out);
}

// round 5
// speedup vs baseline: 3.1986x; 2.5477x over previous
#include <cuda_runtime.h>
#include <math.h>

#define B    8
#define HD   768
#define LP   512
#define LL   256
#define CBN  4096
#define NS   9
#define TT   4

#define OFF_SUM 0
#define OFF_SL  24576
#define OFF_SP  24608
#define OFF_OP  24640
#define OFF_CL  155712

// ---------------- device scratch ----------------
__device__ float g_cat[B * 2 * HD];
__device__ float g_stateA[B * HD];
__device__ float g_stateB[B * HD];
__device__ float g_sq[B * HD];        // accum
__device__ float g_qprime[B * HD];
__device__ float g_scoreS[B * LP];
__device__ float g_u[B * HD];         // accum
__device__ float g_ctx[B * HD];       // accum
__device__ float g_oppre[B * HD];     // accum
__device__ float g_sq2[B * HD];       // accum
__device__ float g_qk2[B * HD];
__device__ float g_sqs[NS * HD];      // accum (precompute)
__device__ float g_sqk2[NS * HD];
__device__ float g_gq[NS];
__device__ float g_glog[B];
__device__ float g_sscore[B * NS * LP];
__device__ float g_wcomb[B * LP];
__device__ float g_uslot[B * HD];     // accum
__device__ float g_ssum[B * HD];      // accum
__device__ float g_msum[B * HD];
__device__ float g_gi[B * 3 * HD];
__device__ float g_gh[B * 3 * HD];
__device__ float g_stoplog[B];
__device__ unsigned long long g_amin[B];

// ---------------- helpers ----------------

// Y[m][j] += sum_{k-split} X[m][k] W[k][j]; CTA layout: jc = cid/nks (3 chunks of 256), ks = cid%nks
template <int M>
__device__ __forceinline__ void colgemv(const float* __restrict__ X, int ldx,
                                        const float* __restrict__ W,
                                        float* __restrict__ Y,
                                        int K, int nks, int cid, float* SM) {
    int jc = cid / nks, ks = cid - jc * nks;
    int j = jc * 256 + threadIdx.x;
    int kr = K / nks, k0 = ks * kr;
    for (int i = threadIdx.x; i < M * kr; i += 256) {
        int m = i / kr, kk = i - m * kr;
        SM[i] = X[(size_t)m * ldx + k0 + kk];
    }
    __syncthreads();
    float acc[M];
#pragma unroll
    for (int m = 0; m < M; m++) acc[m] = 0.f;
#pragma unroll 4
    for (int kk = 0; kk < kr; kk++) {
        float wv = W[(size_t)(k0 + kk) * HD + j];
#pragma unroll
        for (int m = 0; m < M; m++) acc[m] = fmaf(SM[m * kr + kk], wv, acc[m]);
    }
#pragma unroll
    for (int m = 0; m < M; m++) atomicAdd(&Y[(size_t)m * HD + j], acc[m]);
}

// Y[m][n] = sum_k W[n][k] Xg[m][k]; CTAs cid in [0,nc)
template <int M>
__device__ __forceinline__ void rowdot(const float* __restrict__ W,
                                       const float* __restrict__ Xg,
                                       float* __restrict__ Y,
                                       int cid, int nc, float* SM) {
    int tid = threadIdx.x, w = tid >> 5, lane = tid & 31;
    for (int i = tid; i < M * HD; i += 256) SM[i] = Xg[i];
    __syncthreads();
    for (int n = cid * 8 + w; n < HD; n += nc * 8) {
        const float* wr = W + (size_t)n * HD;
        float acc[M];
#pragma unroll
        for (int m = 0; m < M; m++) acc[m] = 0.f;
#pragma unroll 2
        for (int k = lane; k < HD; k += 32) {
            float wv = wr[k];
#pragma unroll
            for (int m = 0; m < M; m++) acc[m] = fmaf(wv, SM[m * HD + k], acc[m]);
        }
#pragma unroll
        for (int m = 0; m < M; m++) {
#pragma unroll
            for (int off = 16; off; off >>= 1)
                acc[m] += __shfl_down_sync(0xffffffffu, acc[m], off);
        }
        if (lane == 0) {
#pragma unroll
            for (int m = 0; m < M; m++) Y[(size_t)m * HD + n] = acc[m];
        }
    }
}

// ---------------- kernels ----------------

__global__ void k_reset() {
    int i = blockIdx.x * 256 + threadIdx.x;
    if (i < B * HD) {
        g_sq[i] = 0.f; g_u[i] = 0.f; g_ctx[i] = 0.f; g_oppre[i] = 0.f;
        g_sq2[i] = 0.f; g_uslot[i] = 0.f; g_ssum[i] = 0.f;
    }
    if (i < NS * HD) g_sqs[i] = 0.f;
    if (i < B) g_amin[i] = 0xFFFFFFFFFFFFFFFFull;
}

// means: 384 warps (48 CTAs x 8)
__global__ void k_pp1(const float* __restrict__ prompt, const float* __restrict__ logic) {
    int w = threadIdx.x >> 5, lane = threadIdx.x & 31;
    int wt = blockIdx.x * 8 + w;
    int which = wt >= 192;
    int t2 = wt - which * 192;
    int b = t2 / 24, hc = t2 - b * 24;
    int h = hc * 32 + lane;
    if (!which) {
        const float* p = prompt + (size_t)b * LP * HD + h;
        float s = 0.f;
#pragma unroll 8
        for (int l = 0; l < LP; l++) s += p[(size_t)l * HD];
        g_cat[b * 2 * HD + h] = s * (1.f / (float)LP);
    } else {
        const float* p = logic + (size_t)b * LL * HD + h;
        float s = 0.f;
#pragma unroll 8
        for (int l = 0; l < LL; l++) s += p[(size_t)l * HD];
        g_cat[b * 2 * HD + HD + h] = s * (1.f / (float)LL);
    }
}

// grid 61: sq += cat@w_init (36), sqs += slot_q@w_slot_q (24), gq (1)
__global__ void k_pp2(const float* __restrict__ w_init, const float* __restrict__ slot_q,
                      const float* __restrict__ w_slot_q, const float* __restrict__ w_gate) {
    __shared__ float SM[1152];
    int cid = blockIdx.x, w = threadIdx.x >> 5, lane = threadIdx.x & 31;
    if (cid < 36) {
        colgemv<8>(g_cat, 2 * HD, w_init, g_sq, 2 * HD, 12, cid, SM);
    } else if (cid < 60) {
        colgemv<9>(slot_q, HD, w_slot_q, g_sqs, HD, 8, cid - 36, SM);
    } else {
        for (int s = w; s < NS; s += 8) {
            float p = 0.f;
            for (int k = lane; k < HD; k += 32)
                p = fmaf(slot_q[s * HD + k], w_gate[k], p);
#pragma unroll
            for (int off = 16; off; off >>= 1) p += __shfl_down_sync(0xffffffffu, p, off);
            if (lane == 0) g_gq[s] = p;
        }
    }
}

// grid 148: stateA = tanh(sq), zero sq (8); sqk2 = w_k@sqs (140)
__global__ void k_pp3(const float* __restrict__ w_k) {
    __shared__ float SM[NS * HD];
    int cid = blockIdx.x, tid = threadIdx.x;
    if (cid < 8) {
        int b = cid;
        for (int rep = 0; rep < 3; rep++) {
            int j = rep * 256 + tid;
            g_stateA[b * HD + j] = tanhf(g_sq[b * HD + j]);
            g_sq[b * HD + j] = 0.f;
        }
    } else {
        rowdot<9>(w_k, g_sqs, g_sqk2, cid - 8, 140, SM);
    }
}

// grid 48: sq += state@w_q
__global__ void k_a(const float* __restrict__ st, const float* __restrict__ w_q) {
    __shared__ float SM[8 * 48];
    colgemv<8>(st, HD, w_q, g_sq, HD, 16, blockIdx.x, SM);
}

// grid 96: qprime = w_k @ sq
__global__ void k_b(const float* __restrict__ w_k) {
    __shared__ float SM[8 * HD];
    rowdot<8>(w_k, g_sq, g_qprime, blockIdx.x, 96, SM);
}

// grid 148: state scores (128) + zero sq (20)
__global__ void k_c(const float* __restrict__ prompt) {
    __shared__ float SM[HD];
    int cid = blockIdx.x, tid = threadIdx.x, w = tid >> 5, lane = tid & 31;
    const float scale = 0.03608439182435161f;
    if (cid < 128) {
        int b = cid >> 4, lc = cid & 15;
        for (int i = tid; i < HD; i += 256) SM[i] = g_qprime[b * HD + i];
        __syncthreads();
        int l0 = lc * 32 + w * 4;
        const float* p0 = prompt + ((size_t)(b * LP + l0)) * HD;
        float a0 = 0.f, a1 = 0.f, a2 = 0.f, a3 = 0.f;
#pragma unroll 2
        for (int k = lane; k < HD; k += 32) {
            float q = SM[k];
            a0 = fmaf(q, p0[k], a0);
            a1 = fmaf(q, p0[HD + k], a1);
            a2 = fmaf(q, p0[2 * HD + k], a2);
            a3 = fmaf(q, p0[3 * HD + k], a3);
        }
#pragma unroll
        for (int off = 16; off; off >>= 1) {
            a0 += __shfl_down_sync(0xffffffffu, a0, off);
            a1 += __shfl_down_sync(0xffffffffu, a1, off);
            a2 += __shfl_down_sync(0xffffffffu, a2, off);
            a3 += __shfl_down_sync(0xffffffffu, a3, off);
        }
        if (lane == 0) {
            g_scoreS[b * LP + l0]     = a0 * scale;
            g_scoreS[b * LP + l0 + 1] = a1 * scale;
            g_scoreS[b * LP + l0 + 2] = a2 * scale;
            g_scoreS[b * LP + l0 + 3] = a3 * scale;
        }
    } else {
        for (int i = (cid - 128) * 256 + tid; i < B * HD; i += 20 * 256) g_sq[i] = 0.f;
    }
}

// grid 96: u += softmax(scoreS) . prompt
__global__ void k_d(const float* __restrict__ prompt) {
    __shared__ float SM[LP];
    __shared__ float SRED[8];
    int cid = blockIdx.x, tid = threadIdx.x, w = tid >> 5, lane = tid & 31;
    int b = cid / 12, rem = cid % 12;
    int jc = rem >> 2, ls = rem & 3;
    int j = jc * 256 + tid;
    SM[tid] = g_scoreS[b * LP + tid];
    SM[tid + 256] = g_scoreS[b * LP + tid + 256];
    __syncthreads();
    float v0 = SM[tid], v1 = SM[tid + 256];
    float mx = fmaxf(v0, v1);
#pragma unroll
    for (int off = 16; off; off >>= 1)
        mx = fmaxf(mx, __shfl_xor_sync(0xffffffffu, mx, off));
    if (lane == 0) SRED[w] = mx;
    __syncthreads();
    mx = SRED[0];
#pragma unroll
    for (int q = 1; q < 8; q++) mx = fmaxf(mx, SRED[q]);
    float e0 = expf(v0 - mx), e1 = expf(v1 - mx);
    float s = e0 + e1;
#pragma unroll
    for (int off = 16; off; off >>= 1) s += __shfl_xor_sync(0xffffffffu, s, off);
    __syncthreads();
    if (lane == 0) SRED[w] = s;
    __syncthreads();
    float tot = 0.f;
#pragma unroll
    for (int q = 0; q < 8; q++) tot += SRED[q];
    float inv = 1.f / tot;
    SM[tid] = e0 * inv; SM[tid + 256] = e1 * inv;
    __syncthreads();
    float acc = 0.f;
    const float* pr = prompt + ((size_t)(b * LP + ls * 128)) * HD + j;
#pragma unroll 8
    for (int l = 0; l < 128; l++) acc = fmaf(SM[ls * 128 + l], pr[(size_t)l * HD], acc);
    atomicAdd(&g_u[b * HD + j], acc);
}

// grid 49: ctx += u @ w_v (48) + reset amin (1)
__global__ void k_e(const float* __restrict__ w_v) {
    __shared__ float SM[8 * 48];
    if (blockIdx.x < 48) colgemv<8>(g_u, HD, w_v, g_ctx, HD, 16, blockIdx.x, SM);
    else if (threadIdx.x < B) g_amin[threadIdx.x] = 0xFFFFFFFFFFFFFFFFull;
}

// grid 122: oppre += ctx@w_op (48), sq2 += ctx@w_slot_q (48), glog (1), stop1 (1), zero u (24)
__global__ void k_f(const float* __restrict__ w_op_pre, const float* __restrict__ w_slot_q,
                    const float* __restrict__ w_gate, const float* __restrict__ w_stop) {
    __shared__ float SM[8 * 48];
    int cid = blockIdx.x, w = threadIdx.x >> 5, lane = threadIdx.x & 31;
    if (cid < 48) colgemv<8>(g_ctx, HD, w_op_pre, g_oppre, HD, 16, cid, SM);
    else if (cid < 96) colgemv<8>(g_ctx, HD, w_slot_q, g_sq2, HD, 16, cid - 48, SM);
    else if (cid == 96) {
        int b = w;
        float p = 0.f;
        for (int k = lane; k < HD; k += 32) p = fmaf(g_ctx[b * HD + k], w_gate[k], p);
#pragma unroll
        for (int off = 16; off; off >>= 1) p += __shfl_down_sync(0xffffffffu, p, off);
        if (lane == 0) g_glog[b] = p;
    } else if (cid == 97) {
        int b = w;
        float p = 0.f;
        for (int k = lane; k < HD; k += 32) p = fmaf(g_ctx[b * HD + k], w_stop[k], p);
#pragma unroll
        for (int off = 16; off; off >>= 1) p += __shfl_down_sync(0xffffffffu, p, off);
        if (lane == 0) g_stoplog[b] = p;
    } else {
        int i = (cid - 98) * 256 + threadIdx.x;
        g_u[i] = 0.f;
    }
}

// grid 148: codebook (118) + qk2 = w_k@sq2 (30)
__global__ void k_g(const float* __restrict__ cbk, const float* __restrict__ w_k,
                    float* __restrict__ out, int t) {
    __shared__ float SM[B * HD];
    int cid = blockIdx.x, tid = threadIdx.x, w = tid >> 5, lane = tid & 31;
    if (cid < 118) {
        for (int i = tid; i < B * HD; i += 256) SM[i] = g_oppre[i];
        __syncthreads();
        for (int c = cid * 8 + w; c < CBN; c += 118 * 8) {
            const float* row = cbk + (size_t)c * HD;
            float acc[B];
#pragma unroll
            for (int m = 0; m < B; m++) acc[m] = 0.f;
#pragma unroll 2
            for (int k = lane; k < HD; k += 32) {
                float v = row[k];
#pragma unroll
                for (int m = 0; m < B; m++) {
                    float d = SM[m * HD + k] - v;
                    acc[m] = fmaf(d, d, acc[m]);
                }
            }
#pragma unroll
            for (int m = 0; m < B; m++) {
#pragma unroll
                for (int off = 16; off; off >>= 1)
                    acc[m] += __shfl_down_sync(0xffffffffu, acc[m], off);
            }
            if (lane == 0) {
#pragma unroll
                for (int m = 0; m < B; m++) {
                    out[OFF_OP + ((size_t)m * TT + t) * CBN + c] = -acc[m];
                    unsigned long long key =
                        ((unsigned long long)__float_as_uint(acc[m]) << 32) | (unsigned)c;
                    atomicMin(&g_amin[m], key);
                }
            }
        }
    } else {
        rowdot<8>(w_k, g_sq2, g_qk2, cid - 118, 30, SM);
    }
}

// grid 148: slot scores (128) + zero ctx/oppre/sq2 (20)
__global__ void k_h(const float* __restrict__ prompt) {
    __shared__ float SM[NS * HD];
    int cid = blockIdx.x, tid = threadIdx.x, w = tid >> 5, lane = tid & 31;
    const float scale = 0.03608439182435161f;
    if (cid < 128) {
        int b = cid >> 4, lc = cid & 15;
        for (int i = tid; i < NS * HD; i += 256) {
            int k = i % HD;
            SM[i] = g_qk2[b * HD + k] + g_sqk2[i];
        }
        __syncthreads();
        for (int li = 0; li < 4; li++) {
            int l = lc * 32 + w * 4 + li;
            const float* pr = prompt + ((size_t)(b * LP + l)) * HD;
            float acc[NS];
#pragma unroll
            for (int s = 0; s < NS; s++) acc[s] = 0.f;
#pragma unroll 2
            for (int k = lane; k < HD; k += 32) {
                float pv = pr[k];
#pragma unroll
                for (int s = 0; s < NS; s++) acc[s] = fmaf(pv, SM[s * HD + k], acc[s]);
            }
#pragma unroll
            for (int s = 0; s < NS; s++) {
#pragma unroll
                for (int off = 16; off; off >>= 1)
                    acc[s] += __shfl_down_sync(0xffffffffu, acc[s], off);
            }
            if (lane == 0) {
#pragma unroll
                for (int s = 0; s < NS; s++)
                    g_sscore[(size_t)(b * NS + s) * LP + l] = acc[s] * scale;
            }
        }
    } else {
        for (int i = (cid - 128) * 256 + tid; i < 3 * B * HD; i += 20 * 256) {
            if (i < B * HD) g_ctx[i] = 0.f;
            else if (i < 2 * B * HD) g_oppre[i - B * HD] = 0.f;
            else g_sq2[i - 2 * B * HD] = 0.f;
        }
    }
}

// grid 8: collapse gates+mask+softmax -> wcomb
__global__ void k_i(const float* __restrict__ b_gate) {
    __shared__ float SM[NS * LP];
    __shared__ float SRED[32];
    int b = blockIdx.x, tid = threadIdx.x, w = tid >> 5, lane = tid & 31;
    float bg = b_gate[0];
    for (int i = tid; i < NS * LP; i += 256) SM[i] = g_sscore[(size_t)b * NS * LP + i];
    int myge = 0;
    if (tid < B * NS) {
        float lg = g_glog[tid / NS] + g_gq[tid % NS] + bg;
        myge = (lg >= 0.f) ? 1 : 0;
    }
    int any = __syncthreads_or(myge);
    if (tid == 0) {
        float cnt = 0.f;
        if (any) {
            for (int s = 0; s < NS; s++) {
                float lg = g_glog[b] + g_gq[s] + bg;
                float m = (lg >= 0.f) ? 1.f : 0.f;
                SRED[s] = m; cnt += m;
            }
        } else {
            int arg = 0; float best = g_glog[b] + g_gq[0] + bg;
            for (int s = 1; s < NS; s++) {
                float v = g_glog[b] + g_gq[s] + bg;
                if (v > best) { best = v; arg = s; }
            }
            for (int s = 0; s < NS; s++) SRED[s] = (s == arg) ? 1.f : 0.f;
            cnt = 1.f;
        }
        SRED[9] = 1.f / fmaxf(cnt, 1.f);
    }
    __syncthreads();
    float invcnt = SRED[9];
    float wa0 = 0.f, wa1 = 0.f;
    for (int s = 0; s < NS; s++) {
        float v0 = SM[s * LP + tid], v1 = SM[s * LP + tid + 256];
        float mx = fmaxf(v0, v1);
#pragma unroll
        for (int off = 16; off; off >>= 1)
            mx = fmaxf(mx, __shfl_xor_sync(0xffffffffu, mx, off));
        if (lane == 0) SRED[10 + w] = mx;
        __syncthreads();
        mx = SRED[10];
#pragma unroll
        for (int q = 1; q < 8; q++) mx = fmaxf(mx, SRED[10 + q]);
        float e0 = expf(v0 - mx), e1 = expf(v1 - mx);
        float sm = e0 + e1;
#pragma unroll
        for (int off = 16; off; off >>= 1) sm += __shfl_xor_sync(0xffffffffu, sm, off);
        __syncthreads();
        if (lane == 0) SRED[18 + w] = sm;
        __syncthreads();
        float tot = 0.f;
#pragma unroll
        for (int q = 0; q < 8; q++) tot += SRED[18 + q];
        float f = SRED[s] * invcnt / tot;
        wa0 = fmaf(e0, f, wa0);
        wa1 = fmaf(e1, f, wa1);
        __syncthreads();
    }
    g_wcomb[b * LP + tid] = wa0;
    g_wcomb[b * LP + tid + 256] = wa1;
}

// grid 96: uslot += wcomb . prompt
__global__ void k_j(const float* __restrict__ prompt) {
    __shared__ float SM[LP];
    int cid = blockIdx.x, tid = threadIdx.x;
    int b = cid / 12, rem = cid % 12;
    int jc = rem >> 2, ls = rem & 3;
    int j = jc * 256 + tid;
    SM[tid] = g_wcomb[b * LP + tid];
    SM[tid + 256] = g_wcomb[b * LP + tid + 256];
    __syncthreads();
    float acc = 0.f;
    const float* pr = prompt + ((size_t)(b * LP + ls * 128)) * HD + j;
#pragma unroll 8
    for (int l = 0; l < 128; l++) acc = fmaf(SM[ls * 128 + l], pr[(size_t)l * HD], acc);
    atomicAdd(&g_uslot[b * HD + j], acc);
}

// grid 48: ssum += uslot @ w_v
__global__ void k_k(const float* __restrict__ w_v) {
    __shared__ float SM[8 * 48];
    colgemv<8>(g_uslot, HD, w_v, g_ssum, HD, 16, blockIdx.x, SM);
}

// grid 32: msum/out (8) + stop2 + zero uslot (24)
__global__ void k_l(const float* __restrict__ cbk, const float* __restrict__ w_stop,
                    float* __restrict__ out, int t) {
    __shared__ float SRED[8];
    int cid = blockIdx.x, tid = threadIdx.x, w = tid >> 5, lane = tid & 31;
    if (cid < 8) {
        int b = cid;
        int idx = (int)(g_amin[b] & 0xFFFFFFFFull);
        float sp = 0.f;
        for (int rep = 0; rep < 3; rep++) {
            int j = rep * 256 + tid;
            float ms = tanhf(cbk[(size_t)idx * HD + j] + g_ssum[b * HD + j]);
            g_msum[b * HD + j] = ms;
            out[OFF_SUM + ((size_t)b * TT + t) * HD + j] = ms;
            sp = fmaf(ms, w_stop[HD + j], sp);
        }
#pragma unroll
        for (int off = 16; off; off >>= 1) sp += __shfl_xor_sync(0xffffffffu, sp, off);
        if (lane == 0) SRED[w] = sp;
        __syncthreads();
        if (tid == 0) {
            float tot = 0.f;
#pragma unroll
            for (int q = 0; q < 8; q++) tot += SRED[q];
            atomicAdd(&g_stoplog[b], tot);
        }
    } else {
        int i = (cid - 8) * 256 + tid;
        g_uslot[i] = 0.f;
    }
}

// grid 148: GRU matvecs gi/gh
__global__ void k_m1(const float* __restrict__ stOld, const float* __restrict__ w_ih,
                     const float* __restrict__ w_hh) {
    __shared__ float SM[B * HD];
    int cid = blockIdx.x, tid = threadIdx.x, w = tid >> 5, lane = tid & 31;
    int half = (cid < 74) ? 0 : 1;
    int base = half ? 74 : 0;
    const float* X = half ? stOld : g_msum;
    const float* W = half ? w_hh : w_ih;
    float* Y = half ? g_gh : g_gi;
    for (int i = tid; i < B * HD; i += 256) SM[i] = X[i];
    __syncthreads();
    for (int n = (cid - base) * 8 + w; n < 3 * HD; n += 74 * 8) {
        const float* wr = W + (size_t)n * HD;
        float acc[B];
#pragma unroll
        for (int m = 0; m < B; m++) acc[m] = 0.f;
#pragma unroll 2
        for (int k = lane; k < HD; k += 32) {
            float wv = wr[k];
#pragma unroll
            for (int m = 0; m < B; m++) acc[m] = fmaf(wv, SM[m * HD + k], acc[m]);
        }
#pragma unroll
        for (int m = 0; m < B; m++) {
#pragma unroll
            for (int off = 16; off; off >>= 1)
                acc[m] += __shfl_down_sync(0xffffffffu, acc[m], off);
        }
        if (lane == 0) {
#pragma unroll
            for (int m = 0; m < B; m++) Y[(size_t)m * 3 * HD + n] = acc[m];
        }
    }
}

// grid 33: GRU combine (8) + SL/SP/CL (1) + zero ssum (24)
__global__ void k_m2(const float* __restrict__ stOld, float* __restrict__ stNew,
                     const float* __restrict__ b_ih, const float* __restrict__ b_hh,
                     const float* __restrict__ b_stop, float* __restrict__ out, int t) {
    int cid = blockIdx.x, tid = threadIdx.x;
    if (cid < 8) {
        int b = cid;
        for (int rep = 0; rep < 3; rep++) {
            int j = rep * 256 + tid;
            float ir = g_gi[b * 3 * HD + j] + b_ih[j];
            float iz = g_gi[b * 3 * HD + HD + j] + b_ih[HD + j];
            float in = g_gi[b * 3 * HD + 2 * HD + j] + b_ih[2 * HD + j];
            float hr = g_gh[b * 3 * HD + j] + b_hh[j];
            float hz = g_gh[b * 3 * HD + HD + j] + b_hh[HD + j];
            float hn = g_gh[b * 3 * HD + 2 * HD + j] + b_hh[2 * HD + j];
            float r = 1.f / (1.f + expf(-(ir + hr)));
            float z = 1.f / (1.f + expf(-(iz + hz)));
            float n = tanhf(in + r * hn);
            stNew[b * HD + j] = (1.f - z) * n + z * stOld[b * HD + j];
        }
    } else if (cid == 8) {
        if (tid == 0) {
            float bs = b_stop[0];
            for (int b = 0; b < B; b++) {
                float lg = g_stoplog[b] + bs;
                out[OFF_SL + b * TT + t] = lg;
                out[OFF_SP + b * TT + t] = 1.f / (1.f + expf(-lg));
            }
            if (t == TT - 1) {
                for (int b = 0; b < B; b++) {
                    int len = TT;
                    for (int tt = 0; tt < TT; tt++)
                        if (out[OFF_SL + b * TT + tt] >= 0.f) { len = tt + 1; break; }
                    out[OFF_CL + b] = (float)len;
                }
            }
        }
    } else {
        int i = (cid - 9) * 256 + tid;
        g_ssum[i] = 0.f;
    }
}

// ---------------- host ----------------
extern "C" void kernel_launch(void* const* d_in, const int* in_sizes, int n_in,
                              void* d_out, int out_size) {
    const float* logic    = (const float*)d_in[0];
    const float* prompt   = (const float*)d_in[1];
    const float* cbk      = (const float*)d_in[2];
    const float* w_init   = (const float*)d_in[3];
    const float* w_q      = (const float*)d_in[4];
    const float* w_k      = (const float*)d_in[5];
    const float* w_v      = (const float*)d_in[6];
    const float* slot_q   = (const float*)d_in[7];
    const float* w_slot_q = (const float*)d_in[8];
    const float* w_op_pre = (const float*)d_in[9];
    const float* w_gate   = (const float*)d_in[10];
    const float* b_gate   = (const float*)d_in[11];
    const float* w_stop   = (const float*)d_in[12];
    const float* b_stop   = (const float*)d_in[13];
    const float* w_ih     = (const float*)d_in[14];
    const float* w_hh     = (const float*)d_in[15];
    const float* b_ih     = (const float*)d_in[16];
    const float* b_hh     = (const float*)d_in[17];
    float* out = (float*)d_out;

    void* p;
    float *stateA, *stateB;
    cudaGetSymbolAddress(&p, g_stateA); stateA = (float*)p;
    cudaGetSymbolAddress(&p, g_stateB); stateB = (float*)p;

    k_reset<<<28, 256>>>();
    k_pp1<<<48, 256>>>(prompt, logic);
    k_pp2<<<61, 256>>>(w_init, slot_q, w_slot_q, w_gate);
    k_pp3<<<148, 256>>>(w_k);

    for (int t = 0; t < TT; t++) {
        float* stOld = (t & 1) ? stateB : stateA;
        float* stNew = (t & 1) ? stateA : stateB;
        k_a<<<48, 256>>>(stOld, w_q);
        k_b<<<96, 256>>>(w_k);
        k_c<<<148, 256>>>(prompt);
        k_d<<<96, 256>>>(prompt);
        k_e<<<49, 256>>>(w_v);
        k_f<<<122, 256>>>(w_op_pre, w_slot_q, w_gate, w_stop);
        k_g<<<148, 256>>>(cbk, w_k, out, t);
        k_h<<<148, 256>>>(prompt);
        k_i<<<8, 256>>>(b_gate);
        k_j<<<96, 256>>>(prompt);
        k_k<<<48, 256>>>(w_v);
        k_l<<<32, 256>>>(cbk, w_stop, out, t);
        k_m1<<<148, 256>>>(stOld, w_ih, w_hh);
        k_m2<<<33, 256>>>(stOld, stNew, b_ih, b_hh, b_stop, out, t);
    }
}

// round 8
// speedup vs baseline: 3.9080x; 1.2218x over previous
#include <cuda_runtime.h>
#include <math.h>

#define B    8
#define HD   768
#define LP   512
#define LL   256
#define CBN  4096
#define NS   9
#define TT   4

#define OFF_SUM 0
#define OFF_SL  24576
#define OFF_SP  24608
#define OFF_OP  24640
#define OFF_CL  155712

// ---------------- device scratch ----------------
__device__ float g_cat[B * 2 * HD];
__device__ float g_stateA[B * HD];
__device__ float g_stateB[B * HD];
__device__ float g_sq[B * HD];
__device__ float g_qprime[B * HD];
__device__ float g_scoreS[B * LP];
__device__ float g_u[B * HD];
__device__ float g_ctx[B * HD];
__device__ float g_oppre[B * HD];
__device__ float g_sq2[B * HD];
__device__ float g_qk2[B * HD];
__device__ float g_sqs[NS * HD];
__device__ float g_sqk2[NS * HD];
__device__ float g_gq[NS];
__device__ float g_glog[B];
__device__ float g_sscore[B * NS * LP];
__device__ float g_wcomb[B * LP];
__device__ float g_uslot[B * HD];
__device__ float g_ssum[B * HD];
__device__ float g_msum[B * HD];
__device__ float g_gi[B * 3 * HD];
__device__ float g_gh[B * 3 * HD];
__device__ float g_stoplog[B];
__device__ unsigned long long g_amin[B];

// ---------------- helpers ----------------

// Y[m][j] += sum_{k-split} X[m][k] W[k][j]
template <int M>
__device__ __forceinline__ void colgemv(const float* __restrict__ X, int ldx,
                                        const float* __restrict__ W,
                                        float* __restrict__ Y,
                                        int K, int nks, int cid, float* SM) {
    int jc = cid / nks, ks = cid - jc * nks;
    int j = jc * 256 + threadIdx.x;
    int kr = K / nks, k0 = ks * kr;
    for (int i = threadIdx.x; i < M * kr; i += 256) {
        int m = i / kr, kk = i - m * kr;
        SM[i] = X[(size_t)m * ldx + k0 + kk];
    }
    __syncthreads();
    float acc[M];
#pragma unroll
    for (int m = 0; m < M; m++) acc[m] = 0.f;
#pragma unroll 8
    for (int kk = 0; kk < kr; kk++) {
        float wv = W[(size_t)(k0 + kk) * HD + j];
#pragma unroll
        for (int m = 0; m < M; m++) acc[m] = fmaf(SM[m * kr + kk], wv, acc[m]);
    }
#pragma unroll
    for (int m = 0; m < M; m++) atomicAdd(&Y[(size_t)m * HD + j], acc[m]);
}

// Y[m][n] = sum_k W[n][k] Xg[m][k]; 1 row per warp pass
template <int M>
__device__ __forceinline__ void rowdot(const float* __restrict__ W,
                                       const float* __restrict__ Xg,
                                       float* __restrict__ Y,
                                       int cid, int nc, float* SM) {
    int tid = threadIdx.x, w = tid >> 5, lane = tid & 31;
    for (int i = tid; i < M * HD; i += 256) SM[i] = Xg[i];
    __syncthreads();
    for (int n = cid * 8 + w; n < HD; n += nc * 8) {
        const float* wr = W + (size_t)n * HD;
        float acc[M];
#pragma unroll
        for (int m = 0; m < M; m++) acc[m] = 0.f;
#pragma unroll 8
        for (int k = lane; k < HD; k += 32) {
            float wv = wr[k];
#pragma unroll
            for (int m = 0; m < M; m++) acc[m] = fmaf(wv, SM[m * HD + k], acc[m]);
        }
#pragma unroll
        for (int m = 0; m < M; m++) {
#pragma unroll
            for (int off = 16; off; off >>= 1)
                acc[m] += __shfl_down_sync(0xffffffffu, acc[m], off);
        }
        if (lane == 0) {
#pragma unroll
            for (int m = 0; m < M; m++) Y[(size_t)m * HD + n] = acc[m];
        }
    }
}

// Y[m][n] = sum_k W[n][k] Xg[m][k]; 4 concurrent rows per warp (MLP boost)
template <int M>
__device__ __forceinline__ void rowdot4(const float* __restrict__ W,
                                        const float* __restrict__ Xg,
                                        float* __restrict__ Y,
                                        int ldy, int Ntot,
                                        int cid, int nc, float* SM) {
    int tid = threadIdx.x, w = tid >> 5, lane = tid & 31;
    for (int i = tid; i < M * HD; i += 256) SM[i] = Xg[i];
    __syncthreads();
    int stride = nc * 8;
    for (int n = cid * 8 + w; n < Ntot; n += 4 * stride) {
        int n1 = n + stride, n2 = n + 2 * stride, n3 = n + 3 * stride;
        bool q1 = n1 < Ntot, q2 = n2 < Ntot, q3 = n3 < Ntot;
        const float* w0 = W + (size_t)n * HD;
        const float* w1 = W + (size_t)(q1 ? n1 : n) * HD;
        const float* w2 = W + (size_t)(q2 ? n2 : n) * HD;
        const float* w3 = W + (size_t)(q3 ? n3 : n) * HD;
        float a0[M], a1[M], a2[M], a3[M];
#pragma unroll
        for (int m = 0; m < M; m++) { a0[m] = 0.f; a1[m] = 0.f; a2[m] = 0.f; a3[m] = 0.f; }
#pragma unroll 2
        for (int k = lane; k < HD; k += 32) {
            float x0 = w0[k], x1 = w1[k], x2 = w2[k], x3 = w3[k];
#pragma unroll
            for (int m = 0; m < M; m++) {
                float s = SM[m * HD + k];
                a0[m] = fmaf(x0, s, a0[m]);
                a1[m] = fmaf(x1, s, a1[m]);
                a2[m] = fmaf(x2, s, a2[m]);
                a3[m] = fmaf(x3, s, a3[m]);
            }
        }
#pragma unroll
        for (int m = 0; m < M; m++) {
            float v0 = a0[m], v1 = a1[m], v2 = a2[m], v3 = a3[m];
#pragma unroll
            for (int off = 16; off; off >>= 1) {
                v0 += __shfl_down_sync(0xffffffffu, v0, off);
                v1 += __shfl_down_sync(0xffffffffu, v1, off);
                v2 += __shfl_down_sync(0xffffffffu, v2, off);
                v3 += __shfl_down_sync(0xffffffffu, v3, off);
            }
            if (lane == 0) {
                Y[(size_t)m * ldy + n] = v0;
                if (q1) Y[(size_t)m * ldy + n1] = v1;
                if (q2) Y[(size_t)m * ldy + n2] = v2;
                if (q3) Y[(size_t)m * ldy + n3] = v3;
            }
        }
    }
}

// ---------------- kernels ----------------

__global__ void k_reset() {
    int i = blockIdx.x * 256 + threadIdx.x;
    if (i < B * HD) {
        g_sq[i] = 0.f; g_u[i] = 0.f; g_ctx[i] = 0.f; g_oppre[i] = 0.f;
        g_sq2[i] = 0.f; g_uslot[i] = 0.f; g_ssum[i] = 0.f;
    }
    if (i < NS * HD) g_sqs[i] = 0.f;
    if (i < B) g_amin[i] = 0xFFFFFFFFFFFFFFFFull;
}

__global__ void k_pp1(const float* __restrict__ prompt, const float* __restrict__ logic) {
    int w = threadIdx.x >> 5, lane = threadIdx.x & 31;
    int wt = blockIdx.x * 8 + w;
    int which = wt >= 192;
    int t2 = wt - which * 192;
    int b = t2 / 24, hc = t2 - b * 24;
    int h = hc * 32 + lane;
    if (!which) {
        const float* p = prompt + (size_t)b * LP * HD + h;
        float s = 0.f;
#pragma unroll 8
        for (int l = 0; l < LP; l++) s += p[(size_t)l * HD];
        g_cat[b * 2 * HD + h] = s * (1.f / (float)LP);
    } else {
        const float* p = logic + (size_t)b * LL * HD + h;
        float s = 0.f;
#pragma unroll 8
        for (int l = 0; l < LL; l++) s += p[(size_t)l * HD];
        g_cat[b * 2 * HD + HD + h] = s * (1.f / (float)LL);
    }
}

__global__ void k_pp2(const float* __restrict__ w_init, const float* __restrict__ slot_q,
                      const float* __restrict__ w_slot_q, const float* __restrict__ w_gate) {
    __shared__ float SM[1152];
    int cid = blockIdx.x, w = threadIdx.x >> 5, lane = threadIdx.x & 31;
    if (cid < 36) {
        colgemv<8>(g_cat, 2 * HD, w_init, g_sq, 2 * HD, 12, cid, SM);
    } else if (cid < 60) {
        colgemv<9>(slot_q, HD, w_slot_q, g_sqs, HD, 8, cid - 36, SM);
    } else {
        for (int s = w; s < NS; s += 8) {
            float p = 0.f;
            for (int k = lane; k < HD; k += 32)
                p = fmaf(slot_q[s * HD + k], w_gate[k], p);
#pragma unroll
            for (int off = 16; off; off >>= 1) p += __shfl_down_sync(0xffffffffu, p, off);
            if (lane == 0) g_gq[s] = p;
        }
    }
}

__global__ void k_pp3(const float* __restrict__ w_k) {
    __shared__ float SM[NS * HD];
    int cid = blockIdx.x, tid = threadIdx.x;
    if (cid < 8) {
        int b = cid;
        for (int rep = 0; rep < 3; rep++) {
            int j = rep * 256 + tid;
            g_stateA[b * HD + j] = tanhf(g_sq[b * HD + j]);
            g_sq[b * HD + j] = 0.f;
        }
    } else {
        rowdot<9>(w_k, g_sqs, g_sqk2, cid - 8, 140, SM);
    }
}

__global__ void k_a(const float* __restrict__ st, const float* __restrict__ w_q) {
    __shared__ float SM[8 * 48];
    colgemv<8>(st, HD, w_q, g_sq, HD, 16, blockIdx.x, SM);
}

__global__ void k_b(const float* __restrict__ w_k) {
    __shared__ float SM[8 * HD];
    rowdot<8>(w_k, g_sq, g_qprime, blockIdx.x, 96, SM);
}

__global__ void k_c(const float* __restrict__ prompt) {
    __shared__ float SM[HD];
    int cid = blockIdx.x, tid = threadIdx.x, w = tid >> 5, lane = tid & 31;
    const float scale = 0.03608439182435161f;
    if (cid < 128) {
        int b = cid >> 4, lc = cid & 15;
        for (int i = tid; i < HD; i += 256) SM[i] = g_qprime[b * HD + i];
        __syncthreads();
        int l0 = lc * 32 + w * 4;
        const float* p0 = prompt + ((size_t)(b * LP + l0)) * HD;
        float a0 = 0.f, a1 = 0.f, a2 = 0.f, a3 = 0.f;
#pragma unroll 2
        for (int k = lane; k < HD; k += 32) {
            float q = SM[k];
            a0 = fmaf(q, p0[k], a0);
            a1 = fmaf(q, p0[HD + k], a1);
            a2 = fmaf(q, p0[2 * HD + k], a2);
            a3 = fmaf(q, p0[3 * HD + k], a3);
        }
#pragma unroll
        for (int off = 16; off; off >>= 1) {
            a0 += __shfl_down_sync(0xffffffffu, a0, off);
            a1 += __shfl_down_sync(0xffffffffu, a1, off);
            a2 += __shfl_down_sync(0xffffffffu, a2, off);
            a3 += __shfl_down_sync(0xffffffffu, a3, off);
        }
        if (lane == 0) {
            g_scoreS[b * LP + l0]     = a0 * scale;
            g_scoreS[b * LP + l0 + 1] = a1 * scale;
            g_scoreS[b * LP + l0 + 2] = a2 * scale;
            g_scoreS[b * LP + l0 + 3] = a3 * scale;
        }
    } else {
        for (int i = (cid - 128) * 256 + tid; i < B * HD; i += 20 * 256) g_sq[i] = 0.f;
    }
}

__global__ void k_d(const float* __restrict__ prompt) {
    __shared__ float SM[LP];
    __shared__ float SRED[8];
    int cid = blockIdx.x, tid = threadIdx.x, w = tid >> 5, lane = tid & 31;
    int b = cid / 12, rem = cid % 12;
    int jc = rem >> 2, ls = rem & 3;
    int j = jc * 256 + tid;
    SM[tid] = g_scoreS[b * LP + tid];
    SM[tid + 256] = g_scoreS[b * LP + tid + 256];
    __syncthreads();
    float v0 = SM[tid], v1 = SM[tid + 256];
    float mx = fmaxf(v0, v1);
#pragma unroll
    for (int off = 16; off; off >>= 1)
        mx = fmaxf(mx, __shfl_xor_sync(0xffffffffu, mx, off));
    if (lane == 0) SRED[w] = mx;
    __syncthreads();
    mx = SRED[0];
#pragma unroll
    for (int q = 1; q < 8; q++) mx = fmaxf(mx, SRED[q]);
    float e0 = expf(v0 - mx), e1 = expf(v1 - mx);
    float s = e0 + e1;
#pragma unroll
    for (int off = 16; off; off >>= 1) s += __shfl_xor_sync(0xffffffffu, s, off);
    __syncthreads();
    if (lane == 0) SRED[w] = s;
    __syncthreads();
    float tot = 0.f;
#pragma unroll
    for (int q = 0; q < 8; q++) tot += SRED[q];
    float inv = 1.f / tot;
    SM[tid] = e0 * inv; SM[tid + 256] = e1 * inv;
    __syncthreads();
    float acc = 0.f;
    const float* pr = prompt + ((size_t)(b * LP + ls * 128)) * HD + j;
#pragma unroll 8
    for (int l = 0; l < 128; l++) acc = fmaf(SM[ls * 128 + l], pr[(size_t)l * HD], acc);
    atomicAdd(&g_u[b * HD + j], acc);
}

__global__ void k_e(const float* __restrict__ w_v) {
    __shared__ float SM[8 * 48];
    if (blockIdx.x < 48) colgemv<8>(g_u, HD, w_v, g_ctx, HD, 16, blockIdx.x, SM);
    else if (threadIdx.x < B) g_amin[threadIdx.x] = 0xFFFFFFFFFFFFFFFFull;
}

__global__ void k_f(const float* __restrict__ w_op_pre, const float* __restrict__ w_slot_q,
                    const float* __restrict__ w_gate, const float* __restrict__ w_stop) {
    __shared__ float SM[8 * 48];
    int cid = blockIdx.x, w = threadIdx.x >> 5, lane = threadIdx.x & 31;
    if (cid < 48) colgemv<8>(g_ctx, HD, w_op_pre, g_oppre, HD, 16, cid, SM);
    else if (cid < 96) colgemv<8>(g_ctx, HD, w_slot_q, g_sq2, HD, 16, cid - 48, SM);
    else if (cid == 96) {
        int b = w;
        float p = 0.f;
        for (int k = lane; k < HD; k += 32) p = fmaf(g_ctx[b * HD + k], w_gate[k], p);
#pragma unroll
        for (int off = 16; off; off >>= 1) p += __shfl_down_sync(0xffffffffu, p, off);
        if (lane == 0) g_glog[b] = p;
    } else if (cid == 97) {
        int b = w;
        float p = 0.f;
        for (int k = lane; k < HD; k += 32) p = fmaf(g_ctx[b * HD + k], w_stop[k], p);
#pragma unroll
        for (int off = 16; off; off >>= 1) p += __shfl_down_sync(0xffffffffu, p, off);
        if (lane == 0) g_stoplog[b] = p;
    } else {
        int i = (cid - 98) * 256 + threadIdx.x;
        g_u[i] = 0.f;
    }
}

// codebook (118 CTAs, 2 rows/warp concurrent) + qk2 = w_k@sq2 (30 CTAs, 4 rows/warp)
__global__ void k_g(const float* __restrict__ cbk, const float* __restrict__ w_k,
                    float* __restrict__ out, int t) {
    __shared__ float SM[B * HD];
    int cid = blockIdx.x, tid = threadIdx.x, w = tid >> 5, lane = tid & 31;
    if (cid < 118) {
        for (int i = tid; i < B * HD; i += 256) SM[i] = g_oppre[i];
        __syncthreads();
        for (int c0 = cid * 8 + w; c0 < CBN; c0 += 2 * 944) {
            int c1 = c0 + 944;
            bool q1 = c1 < CBN;
            const float* r0 = cbk + (size_t)c0 * HD;
            const float* r1 = cbk + (size_t)(q1 ? c1 : c0) * HD;
            float a0[B], a1[B];
#pragma unroll
            for (int m = 0; m < B; m++) { a0[m] = 0.f; a1[m] = 0.f; }
#pragma unroll 4
            for (int k = lane; k < HD; k += 32) {
                float x0 = r0[k], x1 = r1[k];
#pragma unroll
                for (int m = 0; m < B; m++) {
                    float s = SM[m * HD + k];
                    float d0 = s - x0;
                    float d1 = s - x1;
                    a0[m] = fmaf(d0, d0, a0[m]);
                    a1[m] = fmaf(d1, d1, a1[m]);
                }
            }
#pragma unroll
            for (int m = 0; m < B; m++) {
                float v0 = a0[m], v1 = a1[m];
#pragma unroll
                for (int off = 16; off; off >>= 1) {
                    v0 += __shfl_down_sync(0xffffffffu, v0, off);
                    v1 += __shfl_down_sync(0xffffffffu, v1, off);
                }
                if (lane == 0) {
                    out[OFF_OP + ((size_t)m * TT + t) * CBN + c0] = -v0;
                    unsigned long long key0 =
                        ((unsigned long long)__float_as_uint(v0) << 32) | (unsigned)c0;
                    atomicMin(&g_amin[m], key0);
                    if (q1) {
                        out[OFF_OP + ((size_t)m * TT + t) * CBN + c1] = -v1;
                        unsigned long long key1 =
                            ((unsigned long long)__float_as_uint(v1) << 32) | (unsigned)c1;
                        atomicMin(&g_amin[m], key1);
                    }
                }
            }
        }
    } else {
        rowdot4<8>(w_k, g_sq2, g_qk2, HD, HD, cid - 118, 30, SM);
    }
}

// slot scores (128 CTAs, 4 concurrent prompt rows/warp) + zero ctx/oppre/sq2 (20)
__global__ void k_h(const float* __restrict__ prompt) {
    __shared__ float SM[NS * HD];
    int cid = blockIdx.x, tid = threadIdx.x, w = tid >> 5, lane = tid & 31;
    const float scale = 0.03608439182435161f;
    if (cid < 128) {
        int b = cid >> 4, lc = cid & 15;
        for (int i = tid; i < NS * HD; i += 256) {
            int k = i % HD;
            SM[i] = g_qk2[b * HD + k] + g_sqk2[i];
        }
        __syncthreads();
        int l0 = lc * 32 + w * 4;
        const float* p0 = prompt + ((size_t)(b * LP + l0)) * HD;
        float a0[NS], a1[NS], a2[NS], a3[NS];
#pragma unroll
        for (int s = 0; s < NS; s++) { a0[s] = 0.f; a1[s] = 0.f; a2[s] = 0.f; a3[s] = 0.f; }
#pragma unroll 2
        for (int k = lane; k < HD; k += 32) {
            float pv0 = p0[k], pv1 = p0[HD + k], pv2 = p0[2 * HD + k], pv3 = p0[3 * HD + k];
#pragma unroll
            for (int s = 0; s < NS; s++) {
                float q = SM[s * HD + k];
                a0[s] = fmaf(pv0, q, a0[s]);
                a1[s] = fmaf(pv1, q, a1[s]);
                a2[s] = fmaf(pv2, q, a2[s]);
                a3[s] = fmaf(pv3, q, a3[s]);
            }
        }
#pragma unroll
        for (int s = 0; s < NS; s++) {
            float v0 = a0[s], v1 = a1[s], v2 = a2[s], v3 = a3[s];
#pragma unroll
            for (int off = 16; off; off >>= 1) {
                v0 += __shfl_down_sync(0xffffffffu, v0, off);
                v1 += __shfl_down_sync(0xffffffffu, v1, off);
                v2 += __shfl_down_sync(0xffffffffu, v2, off);
                v3 += __shfl_down_sync(0xffffffffu, v3, off);
            }
            if (lane == 0) {
                float* dst = &g_sscore[(size_t)(b * NS + s) * LP + l0];
                dst[0] = v0 * scale;
                dst[1] = v1 * scale;
                dst[2] = v2 * scale;
                dst[3] = v3 * scale;
            }
        }
    } else {
        for (int i = (cid - 128) * 256 + tid; i < 3 * B * HD; i += 20 * 256) {
            if (i < B * HD) g_ctx[i] = 0.f;
            else if (i < 2 * B * HD) g_oppre[i - B * HD] = 0.f;
            else g_sq2[i - 2 * B * HD] = 0.f;
        }
    }
}

__global__ void k_i(const float* __restrict__ b_gate) {
    __shared__ float SM[NS * LP];
    __shared__ float SRED[32];
    int b = blockIdx.x, tid = threadIdx.x, w = tid >> 5, lane = tid & 31;
    float bg = b_gate[0];
    for (int i = tid; i < NS * LP; i += 256) SM[i] = g_sscore[(size_t)b * NS * LP + i];
    int myge = 0;
    if (tid < B * NS) {
        float lg = g_glog[tid / NS] + g_gq[tid % NS] + bg;
        myge = (lg >= 0.f) ? 1 : 0;
    }
    int any = __syncthreads_or(myge);
    if (tid == 0) {
        float cnt = 0.f;
        if (any) {
            for (int s = 0; s < NS; s++) {
                float lg = g_glog[b] + g_gq[s] + bg;
                float m = (lg >= 0.f) ? 1.f : 0.f;
                SRED[s] = m; cnt += m;
            }
        } else {
            int arg = 0; float best = g_glog[b] + g_gq[0] + bg;
            for (int s = 1; s < NS; s++) {
                float v = g_glog[b] + g_gq[s] + bg;
                if (v > best) { best = v; arg = s; }
            }
            for (int s = 0; s < NS; s++) SRED[s] = (s == arg) ? 1.f : 0.f;
            cnt = 1.f;
        }
        SRED[9] = 1.f / fmaxf(cnt, 1.f);
    }
    __syncthreads();
    float invcnt = SRED[9];
    float wa0 = 0.f, wa1 = 0.f;
    for (int s = 0; s < NS; s++) {
        float v0 = SM[s * LP + tid], v1 = SM[s * LP + tid + 256];
        float mx = fmaxf(v0, v1);
#pragma unroll
        for (int off = 16; off; off >>= 1)
            mx = fmaxf(mx, __shfl_xor_sync(0xffffffffu, mx, off));
        if (lane == 0) SRED[10 + w] = mx;
        __syncthreads();
        mx = SRED[10];
#pragma unroll
        for (int q = 1; q < 8; q++) mx = fmaxf(mx, SRED[10 + q]);
        float e0 = expf(v0 - mx), e1 = expf(v1 - mx);
        float sm = e0 + e1;
#pragma unroll
        for (int off = 16; off; off >>= 1) sm += __shfl_xor_sync(0xffffffffu, sm, off);
        __syncthreads();
        if (lane == 0) SRED[18 + w] = sm;
        __syncthreads();
        float tot = 0.f;
#pragma unroll
        for (int q = 0; q < 8; q++) tot += SRED[18 + q];
        float f = SRED[s] * invcnt / tot;
        wa0 = fmaf(e0, f, wa0);
        wa1 = fmaf(e1, f, wa1);
        __syncthreads();
    }
    g_wcomb[b * LP + tid] = wa0;
    g_wcomb[b * LP + tid + 256] = wa1;
}

__global__ void k_j(const float* __restrict__ prompt) {
    __shared__ float SM[LP];
    int cid = blockIdx.x, tid = threadIdx.x;
    int b = cid / 12, rem = cid % 12;
    int jc = rem >> 2, ls = rem & 3;
    int j = jc * 256 + tid;
    SM[tid] = g_wcomb[b * LP + tid];
    SM[tid + 256] = g_wcomb[b * LP + tid + 256];
    __syncthreads();
    float acc = 0.f;
    const float* pr = prompt + ((size_t)(b * LP + ls * 128)) * HD + j;
#pragma unroll 8
    for (int l = 0; l < 128; l++) acc = fmaf(SM[ls * 128 + l], pr[(size_t)l * HD], acc);
    atomicAdd(&g_uslot[b * HD + j], acc);
}

__global__ void k_k(const float* __restrict__ w_v) {
    __shared__ float SM[8 * 48];
    colgemv<8>(g_uslot, HD, w_v, g_ssum, HD, 16, blockIdx.x, SM);
}

__global__ void k_l(const float* __restrict__ cbk, const float* __restrict__ w_stop,
                    float* __restrict__ out, int t) {
    __shared__ float SRED[8];
    int cid = blockIdx.x, tid = threadIdx.x, w = tid >> 5, lane = tid & 31;
    if (cid < 8) {
        int b = cid;
        int idx = (int)(g_amin[b] & 0xFFFFFFFFull);
        float sp = 0.f;
        for (int rep = 0; rep < 3; rep++) {
            int j = rep * 256 + tid;
            float ms = tanhf(cbk[(size_t)idx * HD + j] + g_ssum[b * HD + j]);
            g_msum[b * HD + j] = ms;
            out[OFF_SUM + ((size_t)b * TT + t) * HD + j] = ms;
            sp = fmaf(ms, w_stop[HD + j], sp);
        }
#pragma unroll
        for (int off = 16; off; off >>= 1) sp += __shfl_xor_sync(0xffffffffu, sp, off);
        if (lane == 0) SRED[w] = sp;
        __syncthreads();
        if (tid == 0) {
            float tot = 0.f;
#pragma unroll
            for (int q = 0; q < 8; q++) tot += SRED[q];
            atomicAdd(&g_stoplog[b], tot);
        }
    } else {
        int i = (cid - 8) * 256 + tid;
        g_uslot[i] = 0.f;
    }
}

// GRU matvecs: 4 concurrent rows/warp via rowdot4
__global__ void k_m1(const float* __restrict__ stOld, const float* __restrict__ w_ih,
                     const float* __restrict__ w_hh) {
    __shared__ float SM[B * HD];
    int cid = blockIdx.x;
    int half = (cid < 74) ? 0 : 1;
    int base = half ? 74 : 0;
    const float* X = half ? stOld : g_msum;
    const float* W = half ? w_hh : w_ih;
    float* Y = half ? g_gh : g_gi;
    rowdot4<8>(W, X, Y, 3 * HD, 3 * HD, cid - base, 74, SM);
}

__global__ void k_m2(const float* __restrict__ stOld, float* __restrict__ stNew,
                     const float* __restrict__ b_ih, const float* __restrict__ b_hh,
                     const float* __restrict__ b_stop, float* __restrict__ out, int t) {
    int cid = blockIdx.x, tid = threadIdx.x;
    if (cid < 8) {
        int b = cid;
        for (int rep = 0; rep < 3; rep++) {
            int j = rep * 256 + tid;
            float ir = g_gi[b * 3 * HD + j] + b_ih[j];
            float iz = g_gi[b * 3 * HD + HD + j] + b_ih[HD + j];
            float in = g_gi[b * 3 * HD + 2 * HD + j] + b_ih[2 * HD + j];
            float hr = g_gh[b * 3 * HD + j] + b_hh[j];
            float hz = g_gh[b * 3 * HD + HD + j] + b_hh[HD + j];
            float hn = g_gh[b * 3 * HD + 2 * HD + j] + b_hh[2 * HD + j];
            float r = 1.f / (1.f + expf(-(ir + hr)));
            float z = 1.f / (1.f + expf(-(iz + hz)));
            float n = tanhf(in + r * hn);
            stNew[b * HD + j] = (1.f - z) * n + z * stOld[b * HD + j];
        }
    } else if (cid == 8) {
        if (tid == 0) {
            float bs = b_stop[0];
            for (int b = 0; b < B; b++) {
                float lg = g_stoplog[b] + bs;
                out[OFF_SL + b * TT + t] = lg;
                out[OFF_SP + b * TT + t] = 1.f / (1.f + expf(-lg));
                g_stoplog[b] = 0.f;
            }
            if (t == TT - 1) {
                for (int b = 0; b < B; b++) {
                    int len = TT;
                    for (int tt = 0; tt < TT; tt++)
                        if (out[OFF_SL + b * TT + tt] >= 0.f) { len = tt + 1; break; }
                    out[OFF_CL + b] = (float)len;
                }
            }
        }
    } else {
        int i = (cid - 9) * 256 + tid;
        g_ssum[i] = 0.f;
    }
}

// ---------------- host ----------------
extern "C" void kernel_launch(void* const* d_in, const int* in_sizes, int n_in,
                              void* d_out, int out_size) {
    const float* logic    = (const float*)d_in[0];
    const float* prompt   = (const float*)d_in[1];
    const float* cbk      = (const float*)d_in[2];
    const float* w_init   = (const float*)d_in[3];
    const float* w_q      = (const float*)d_in[4];
    const float* w_k      = (const float*)d_in[5];
    const float* w_v      = (const float*)d_in[6];
    const float* slot_q   = (const float*)d_in[7];
    const float* w_slot_q = (const float*)d_in[8];
    const float* w_op_pre = (const float*)d_in[9];
    const float* w_gate   = (const float*)d_in[10];
    const float* b_gate   = (const float*)d_in[11];
    const float* w_stop   = (const float*)d_in[12];
    const float* b_stop   = (const float*)d_in[13];
    const float* w_ih     = (const float*)d_in[14];
    const float* w_hh     = (const float*)d_in[15];
    const float* b_ih     = (const float*)d_in[16];
    const float* b_hh     = (const float*)d_in[17];
    float* out = (float*)d_out;

    void* p;
    float *stateA, *stateB;
    cudaGetSymbolAddress(&p, g_stateA); stateA = (float*)p;
    cudaGetSymbolAddress(&p, g_stateB); stateB = (float*)p;

    k_reset<<<28, 256>>>();
    k_pp1<<<48, 256>>>(prompt, logic);
    k_pp2<<<61, 256>>>(w_init, slot_q, w_slot_q, w_gate);
    k_pp3<<<148, 256>>>(w_k);

    for (int t = 0; t < TT; t++) {
        float* stOld = (t & 1) ? stateB : stateA;
        float* stNew = (t & 1) ? stateA : stateB;
        k_a<<<48, 256>>>(stOld, w_q);
        k_b<<<96, 256>>>(w_k);
        k_c<<<148, 256>>>(prompt);
        k_d<<<96, 256>>>(prompt);
        k_e<<<49, 256>>>(w_v);
        k_f<<<122, 256>>>(w_op_pre, w_slot_q, w_gate, w_stop);
        k_g<<<148, 256>>>(cbk, w_k, out, t);
        k_h<<<148, 256>>>(prompt);
        k_i<<<8, 256>>>(b_gate);
        k_j<<<96, 256>>>(prompt);
        k_k<<<48, 256>>>(w_v);
        k_l<<<32, 256>>>(cbk, w_stop, out, t);
        k_m1<<<148, 256>>>(stOld, w_ih, w_hh);
        k_m2<<<33, 256>>>(stOld, stNew, b_ih, b_hh, b_stop, out, t);
    }
}

// round 9
// speedup vs baseline: 3.9379x; 1.0077x over previous
#include <cuda_runtime.h>
#include <math.h>

#define B    8
#define HD   768
#define HD4  192
#define LP   512
#define LL   256
#define CBN  4096
#define NS   9
#define TT   4

#define OFF_SUM 0
#define OFF_SL  24576
#define OFF_SP  24608
#define OFF_OP  24640
#define OFF_CL  155712

// ---------------- device scratch ----------------
__device__ __align__(16) float g_cat[B * 2 * HD];
__device__ __align__(16) float g_stateA[B * HD];
__device__ __align__(16) float g_stateB[B * HD];
__device__ __align__(16) float g_sq[B * HD];
__device__ __align__(16) float g_qprime[B * HD];
__device__ __align__(16) float g_scoreS[B * LP];
__device__ __align__(16) float g_u[B * HD];
__device__ __align__(16) float g_ctx[B * HD];
__device__ __align__(16) float g_oppre[B * HD];
__device__ __align__(16) float g_sq2[B * HD];
__device__ __align__(16) float g_qk2[B * HD];
__device__ __align__(16) float g_sqs[NS * HD];
__device__ __align__(16) float g_sqk2[NS * HD];
__device__ float g_gq[NS];
__device__ float g_glog[B];
__device__ __align__(16) float g_sscore[B * NS * LP];
__device__ __align__(16) float g_wcomb[B * LP];
__device__ __align__(16) float g_uslot[B * HD];
__device__ __align__(16) float g_ssum[B * HD];
__device__ __align__(16) float g_msum[B * HD];
__device__ __align__(16) float g_gi[B * 3 * HD];
__device__ __align__(16) float g_gh[B * 3 * HD];
__device__ float g_stoplog[B];
__device__ unsigned long long g_amin[B];

// ---------------- helpers ----------------

#define FMA4(ACC, A, Bv) \
    ACC.x = fmaf(A, Bv.x, ACC.x); ACC.y = fmaf(A, Bv.y, ACC.y); \
    ACC.z = fmaf(A, Bv.z, ACC.z); ACC.w = fmaf(A, Bv.w, ACC.w);

// Y[m][4t+c] += sum_{k-split} X[m][k] W[k][4t+c]; 192 compute threads, float4 over j
template <int M>
__device__ __forceinline__ void colgemv4(const float* __restrict__ X, int ldx,
                                         const float* __restrict__ W,
                                         float* __restrict__ Y,
                                         int K, int nks, int cid, float* SM) {
    int kr = K / nks, k0 = cid * kr;
    for (int i = threadIdx.x; i < M * kr; i += 256) {
        int m = i / kr, kk = i - m * kr;
        SM[i] = X[(size_t)m * ldx + k0 + kk];
    }
    __syncthreads();
    if (threadIdx.x < HD4) {
        const float4* W4 = reinterpret_cast<const float4*>(W);
        float4 acc[M];
#pragma unroll
        for (int m = 0; m < M; m++) acc[m] = make_float4(0.f, 0.f, 0.f, 0.f);
#pragma unroll 4
        for (int kk = 0; kk < kr; kk++) {
            float4 wv = W4[(size_t)(k0 + kk) * HD4 + threadIdx.x];
#pragma unroll
            for (int m = 0; m < M; m++) {
                float s = SM[m * kr + kk];
                FMA4(acc[m], s, wv);
            }
        }
        int j = threadIdx.x * 4;
#pragma unroll
        for (int m = 0; m < M; m++) {
            atomicAdd(&Y[(size_t)m * HD + j],     acc[m].x);
            atomicAdd(&Y[(size_t)m * HD + j + 1], acc[m].y);
            atomicAdd(&Y[(size_t)m * HD + j + 2], acc[m].z);
            atomicAdd(&Y[(size_t)m * HD + j + 3], acc[m].w);
        }
    }
}

// Y[m][n] = sum_k W[n][k] Xg[m][k]; float4 over k (6 LDG.128 per row)
template <int M>
__device__ __forceinline__ void rowdot(const float* __restrict__ W,
                                       const float* __restrict__ Xg,
                                       float* __restrict__ Y,
                                       int cid, int nc, float* SM) {
    int tid = threadIdx.x, w = tid >> 5, lane = tid & 31;
    for (int i = tid; i < M * HD; i += 256) SM[i] = Xg[i];
    __syncthreads();
    const float4* SM4 = reinterpret_cast<const float4*>(SM);
    for (int n = cid * 8 + w; n < HD; n += nc * 8) {
        const float4* wr = reinterpret_cast<const float4*>(W + (size_t)n * HD);
        float acc[M];
#pragma unroll
        for (int m = 0; m < M; m++) acc[m] = 0.f;
#pragma unroll
        for (int k = lane; k < HD4; k += 32) {
            float4 wv = wr[k];
#pragma unroll
            for (int m = 0; m < M; m++) {
                float4 s = SM4[m * HD4 + k];
                acc[m] = fmaf(wv.x, s.x, acc[m]);
                acc[m] = fmaf(wv.y, s.y, acc[m]);
                acc[m] = fmaf(wv.z, s.z, acc[m]);
                acc[m] = fmaf(wv.w, s.w, acc[m]);
            }
        }
#pragma unroll
        for (int m = 0; m < M; m++) {
#pragma unroll
            for (int off = 16; off; off >>= 1)
                acc[m] += __shfl_down_sync(0xffffffffu, acc[m], off);
        }
        if (lane == 0) {
#pragma unroll
            for (int m = 0; m < M; m++) Y[(size_t)m * HD + n] = acc[m];
        }
    }
}

// Y[m][n]; 4 concurrent rows per warp, float4 over k
template <int M>
__device__ __forceinline__ void rowdot4(const float* __restrict__ W,
                                        const float* __restrict__ Xg,
                                        float* __restrict__ Y,
                                        int ldy, int Ntot,
                                        int cid, int nc, float* SM) {
    int tid = threadIdx.x, w = tid >> 5, lane = tid & 31;
    for (int i = tid; i < M * HD; i += 256) SM[i] = Xg[i];
    __syncthreads();
    const float4* SM4 = reinterpret_cast<const float4*>(SM);
    int stride = nc * 8;
    for (int n = cid * 8 + w; n < Ntot; n += 4 * stride) {
        int n1 = n + stride, n2 = n + 2 * stride, n3 = n + 3 * stride;
        bool q1 = n1 < Ntot, q2 = n2 < Ntot, q3 = n3 < Ntot;
        const float4* w0 = reinterpret_cast<const float4*>(W + (size_t)n * HD);
        const float4* w1 = reinterpret_cast<const float4*>(W + (size_t)(q1 ? n1 : n) * HD);
        const float4* w2 = reinterpret_cast<const float4*>(W + (size_t)(q2 ? n2 : n) * HD);
        const float4* w3 = reinterpret_cast<const float4*>(W + (size_t)(q3 ? n3 : n) * HD);
        float a0[M], a1[M], a2[M], a3[M];
#pragma unroll
        for (int m = 0; m < M; m++) { a0[m] = 0.f; a1[m] = 0.f; a2[m] = 0.f; a3[m] = 0.f; }
#pragma unroll 2
        for (int k = lane; k < HD4; k += 32) {
            float4 x0 = w0[k], x1 = w1[k], x2 = w2[k], x3 = w3[k];
#pragma unroll
            for (int m = 0; m < M; m++) {
                float4 s = SM4[m * HD4 + k];
                a0[m] = fmaf(x0.x, s.x, a0[m]); a0[m] = fmaf(x0.y, s.y, a0[m]);
                a0[m] = fmaf(x0.z, s.z, a0[m]); a0[m] = fmaf(x0.w, s.w, a0[m]);
                a1[m] = fmaf(x1.x, s.x, a1[m]); a1[m] = fmaf(x1.y, s.y, a1[m]);
                a1[m] = fmaf(x1.z, s.z, a1[m]); a1[m] = fmaf(x1.w, s.w, a1[m]);
                a2[m] = fmaf(x2.x, s.x, a2[m]); a2[m] = fmaf(x2.y, s.y, a2[m]);
                a2[m] = fmaf(x2.z, s.z, a2[m]); a2[m] = fmaf(x2.w, s.w, a2[m]);
                a3[m] = fmaf(x3.x, s.x, a3[m]); a3[m] = fmaf(x3.y, s.y, a3[m]);
                a3[m] = fmaf(x3.z, s.z, a3[m]); a3[m] = fmaf(x3.w, s.w, a3[m]);
            }
        }
#pragma unroll
        for (int m = 0; m < M; m++) {
            float v0 = a0[m], v1 = a1[m], v2 = a2[m], v3 = a3[m];
#pragma unroll
            for (int off = 16; off; off >>= 1) {
                v0 += __shfl_down_sync(0xffffffffu, v0, off);
                v1 += __shfl_down_sync(0xffffffffu, v1, off);
                v2 += __shfl_down_sync(0xffffffffu, v2, off);
                v3 += __shfl_down_sync(0xffffffffu, v3, off);
            }
            if (lane == 0) {
                Y[(size_t)m * ldy + n] = v0;
                if (q1) Y[(size_t)m * ldy + n1] = v1;
                if (q2) Y[(size_t)m * ldy + n2] = v2;
                if (q3) Y[(size_t)m * ldy + n3] = v3;
            }
        }
    }
}

// ---------------- kernels ----------------

__global__ void k_reset() {
    int i = blockIdx.x * 256 + threadIdx.x;
    if (i < B * HD) {
        g_sq[i] = 0.f; g_u[i] = 0.f; g_ctx[i] = 0.f; g_oppre[i] = 0.f;
        g_sq2[i] = 0.f; g_uslot[i] = 0.f; g_ssum[i] = 0.f;
    }
    if (i < NS * HD) g_sqs[i] = 0.f;
    if (i < B) { g_amin[i] = 0xFFFFFFFFFFFFFFFFull; g_stoplog[i] = 0.f; }
}

// means, float4 over h: 96 warps (12 CTAs x 8)
__global__ void k_pp1(const float* __restrict__ prompt, const float* __restrict__ logic) {
    int w = threadIdx.x >> 5, lane = threadIdx.x & 31;
    int wt = blockIdx.x * 8 + w;
    if (wt < 48) {
        int b = wt / 6, hc = wt % 6;
        int h4 = hc * 32 + lane;
        const float4* p = reinterpret_cast<const float4*>(prompt + (size_t)b * LP * HD);
        float4 s = make_float4(0.f, 0.f, 0.f, 0.f);
#pragma unroll 8
        for (int l = 0; l < LP; l++) {
            float4 v = p[(size_t)l * HD4 + h4];
            s.x += v.x; s.y += v.y; s.z += v.z; s.w += v.w;
        }
        int h = h4 * 4;
        float inv = 1.f / (float)LP;
        g_cat[b * 2 * HD + h]     = s.x * inv;
        g_cat[b * 2 * HD + h + 1] = s.y * inv;
        g_cat[b * 2 * HD + h + 2] = s.z * inv;
        g_cat[b * 2 * HD + h + 3] = s.w * inv;
    } else {
        int t2 = wt - 48;
        int b = t2 / 6, hc = t2 % 6;
        int h4 = hc * 32 + lane;
        const float4* p = reinterpret_cast<const float4*>(logic + (size_t)b * LL * HD);
        float4 s = make_float4(0.f, 0.f, 0.f, 0.f);
#pragma unroll 8
        for (int l = 0; l < LL; l++) {
            float4 v = p[(size_t)l * HD4 + h4];
            s.x += v.x; s.y += v.y; s.z += v.z; s.w += v.w;
        }
        int h = h4 * 4;
        float inv = 1.f / (float)LL;
        g_cat[b * 2 * HD + HD + h]     = s.x * inv;
        g_cat[b * 2 * HD + HD + h + 1] = s.y * inv;
        g_cat[b * 2 * HD + HD + h + 2] = s.z * inv;
        g_cat[b * 2 * HD + HD + h + 3] = s.w * inv;
    }
}

// grid 49: sq += cat@w_init (32), sqs += slot_q@w_slot_q (16), gq (1)
__global__ void k_pp2(const float* __restrict__ w_init, const float* __restrict__ slot_q,
                      const float* __restrict__ w_slot_q, const float* __restrict__ w_gate) {
    __shared__ __align__(16) float SM[9 * 48];
    int cid = blockIdx.x, w = threadIdx.x >> 5, lane = threadIdx.x & 31;
    if (cid < 32) {
        colgemv4<8>(g_cat, 2 * HD, w_init, g_sq, 2 * HD, 32, cid, SM);
    } else if (cid < 48) {
        colgemv4<9>(slot_q, HD, w_slot_q, g_sqs, HD, 16, cid - 32, SM);
    } else {
        for (int s = w; s < NS; s += 8) {
            float p = 0.f;
            for (int k = lane; k < HD; k += 32)
                p = fmaf(slot_q[s * HD + k], w_gate[k], p);
#pragma unroll
            for (int off = 16; off; off >>= 1) p += __shfl_down_sync(0xffffffffu, p, off);
            if (lane == 0) g_gq[s] = p;
        }
    }
}

__global__ void k_pp3(const float* __restrict__ w_k) {
    __shared__ __align__(16) float SM[NS * HD];
    int cid = blockIdx.x, tid = threadIdx.x;
    if (cid < 8) {
        int b = cid;
        for (int rep = 0; rep < 3; rep++) {
            int j = rep * 256 + tid;
            g_stateA[b * HD + j] = tanhf(g_sq[b * HD + j]);
            g_sq[b * HD + j] = 0.f;
        }
    } else {
        rowdot<9>(w_k, g_sqs, g_sqk2, cid - 8, 140, SM);
    }
}

// grid 32: sq += state@w_q
__global__ void k_a(const float* __restrict__ st, const float* __restrict__ w_q) {
    __shared__ __align__(16) float SM[8 * 24];
    colgemv4<8>(st, HD, w_q, g_sq, HD, 32, blockIdx.x, SM);
}

// grid 96: qprime = w_k @ sq
__global__ void k_b(const float* __restrict__ w_k) {
    __shared__ __align__(16) float SM[8 * HD];
    rowdot<8>(w_k, g_sq, g_qprime, blockIdx.x, 96, SM);
}

// grid 148: state scores (128, float4 over k) + zero sq (20)
__global__ void k_c(const float* __restrict__ prompt) {
    __shared__ __align__(16) float SM[HD];
    int cid = blockIdx.x, tid = threadIdx.x, w = tid >> 5, lane = tid & 31;
    const float scale = 0.03608439182435161f;
    if (cid < 128) {
        int b = cid >> 4, lc = cid & 15;
        for (int i = tid; i < HD; i += 256) SM[i] = g_qprime[b * HD + i];
        __syncthreads();
        const float4* SM4 = reinterpret_cast<const float4*>(SM);
        int l0 = lc * 32 + w * 4;
        const float4* p0 = reinterpret_cast<const float4*>(prompt + ((size_t)(b * LP + l0)) * HD);
        float a0 = 0.f, a1 = 0.f, a2 = 0.f, a3 = 0.f;
#pragma unroll 2
        for (int k = lane; k < HD4; k += 32) {
            float4 q = SM4[k];
            float4 v0 = p0[k], v1 = p0[HD4 + k], v2 = p0[2 * HD4 + k], v3 = p0[3 * HD4 + k];
            a0 = fmaf(q.x, v0.x, a0); a0 = fmaf(q.y, v0.y, a0);
            a0 = fmaf(q.z, v0.z, a0); a0 = fmaf(q.w, v0.w, a0);
            a1 = fmaf(q.x, v1.x, a1); a1 = fmaf(q.y, v1.y, a1);
            a1 = fmaf(q.z, v1.z, a1); a1 = fmaf(q.w, v1.w, a1);
            a2 = fmaf(q.x, v2.x, a2); a2 = fmaf(q.y, v2.y, a2);
            a2 = fmaf(q.z, v2.z, a2); a2 = fmaf(q.w, v2.w, a2);
            a3 = fmaf(q.x, v3.x, a3); a3 = fmaf(q.y, v3.y, a3);
            a3 = fmaf(q.z, v3.z, a3); a3 = fmaf(q.w, v3.w, a3);
        }
#pragma unroll
        for (int off = 16; off; off >>= 1) {
            a0 += __shfl_down_sync(0xffffffffu, a0, off);
            a1 += __shfl_down_sync(0xffffffffu, a1, off);
            a2 += __shfl_down_sync(0xffffffffu, a2, off);
            a3 += __shfl_down_sync(0xffffffffu, a3, off);
        }
        if (lane == 0) {
            g_scoreS[b * LP + l0]     = a0 * scale;
            g_scoreS[b * LP + l0 + 1] = a1 * scale;
            g_scoreS[b * LP + l0 + 2] = a2 * scale;
            g_scoreS[b * LP + l0 + 3] = a3 * scale;
        }
    } else {
        for (int i = (cid - 128) * 256 + tid; i < B * HD; i += 20 * 256) g_sq[i] = 0.f;
    }
}

// grid 64 (8b x 8ls): u += softmax(scoreS) . prompt, float4 over j
__global__ void k_d(const float* __restrict__ prompt) {
    __shared__ __align__(16) float SW[LP];
    __shared__ float SRED[8];
    int cid = blockIdx.x, tid = threadIdx.x, w = tid >> 5, lane = tid & 31;
    int b = cid >> 3, ls = cid & 7;
    SW[tid] = g_scoreS[b * LP + tid];
    SW[tid + 256] = g_scoreS[b * LP + tid + 256];
    __syncthreads();
    float v0 = SW[tid], v1 = SW[tid + 256];
    float mx = fmaxf(v0, v1);
#pragma unroll
    for (int off = 16; off; off >>= 1)
        mx = fmaxf(mx, __shfl_xor_sync(0xffffffffu, mx, off));
    if (lane == 0) SRED[w] = mx;
    __syncthreads();
    mx = SRED[0];
#pragma unroll
    for (int q = 1; q < 8; q++) mx = fmaxf(mx, SRED[q]);
    float e0 = expf(v0 - mx), e1 = expf(v1 - mx);
    float s = e0 + e1;
#pragma unroll
    for (int off = 16; off; off >>= 1) s += __shfl_xor_sync(0xffffffffu, s, off);
    __syncthreads();
    if (lane == 0) SRED[w] = s;
    __syncthreads();
    float tot = 0.f;
#pragma unroll
    for (int q = 0; q < 8; q++) tot += SRED[q];
    float inv = 1.f / tot;
    SW[tid] = e0 * inv; SW[tid + 256] = e1 * inv;
    __syncthreads();
    if (tid < HD4) {
        const float4* pr4 = reinterpret_cast<const float4*>(
            prompt + ((size_t)(b * LP + ls * 64)) * HD);
        float4 acc = make_float4(0.f, 0.f, 0.f, 0.f);
#pragma unroll 4
        for (int l = 0; l < 64; l++) {
            float wv = SW[ls * 64 + l];
            float4 p = pr4[(size_t)l * HD4 + tid];
            FMA4(acc, wv, p);
        }
        int j = tid * 4;
        atomicAdd(&g_u[b * HD + j],     acc.x);
        atomicAdd(&g_u[b * HD + j + 1], acc.y);
        atomicAdd(&g_u[b * HD + j + 2], acc.z);
        atomicAdd(&g_u[b * HD + j + 3], acc.w);
    }
}

// grid 33: ctx += u @ w_v (32) + reset amin (1)
__global__ void k_e(const float* __restrict__ w_v) {
    __shared__ __align__(16) float SM[8 * 24];
    if (blockIdx.x < 32) colgemv4<8>(g_u, HD, w_v, g_ctx, HD, 32, blockIdx.x, SM);
    else if (threadIdx.x < B) g_amin[threadIdx.x] = 0xFFFFFFFFFFFFFFFFull;
}

// grid 90: oppre (32), sq2 (32), glog (1), stop1 (1), zero u (24)
__global__ void k_f(const float* __restrict__ w_op_pre, const float* __restrict__ w_slot_q,
                    const float* __restrict__ w_gate, const float* __restrict__ w_stop) {
    __shared__ __align__(16) float SM[8 * 24];
    int cid = blockIdx.x, w = threadIdx.x >> 5, lane = threadIdx.x & 31;
    if (cid < 32) colgemv4<8>(g_ctx, HD, w_op_pre, g_oppre, HD, 32, cid, SM);
    else if (cid < 64) colgemv4<8>(g_ctx, HD, w_slot_q, g_sq2, HD, 32, cid - 32, SM);
    else if (cid == 64) {
        int b = w;
        float p = 0.f;
        for (int k = lane; k < HD; k += 32) p = fmaf(g_ctx[b * HD + k], w_gate[k], p);
#pragma unroll
        for (int off = 16; off; off >>= 1) p += __shfl_down_sync(0xffffffffu, p, off);
        if (lane == 0) g_glog[b] = p;
    } else if (cid == 65) {
        int b = w;
        float p = 0.f;
        for (int k = lane; k < HD; k += 32) p = fmaf(g_ctx[b * HD + k], w_stop[k], p);
#pragma unroll
        for (int off = 16; off; off >>= 1) p += __shfl_down_sync(0xffffffffu, p, off);
        if (lane == 0) g_stoplog[b] = p;
    } else {
        int i = (cid - 66) * 256 + threadIdx.x;
        g_u[i] = 0.f;
    }
}

// codebook (118 CTAs, 2 rows/warp, float4) + qk2 = w_k@sq2 (30 CTAs, rowdot4)
__global__ void k_g(const float* __restrict__ cbk, const float* __restrict__ w_k,
                    float* __restrict__ out, int t) {
    __shared__ __align__(16) float SM[B * HD];
    int cid = blockIdx.x, tid = threadIdx.x, w = tid >> 5, lane = tid & 31;
    if (cid < 118) {
        for (int i = tid; i < B * HD; i += 256) SM[i] = g_oppre[i];
        __syncthreads();
        const float4* SM4 = reinterpret_cast<const float4*>(SM);
        for (int c0 = cid * 8 + w; c0 < CBN; c0 += 2 * 944) {
            int c1 = c0 + 944;
            bool q1 = c1 < CBN;
            const float4* r0 = reinterpret_cast<const float4*>(cbk + (size_t)c0 * HD);
            const float4* r1 = reinterpret_cast<const float4*>(cbk + (size_t)(q1 ? c1 : c0) * HD);
            float a0[B], a1[B];
#pragma unroll
            for (int m = 0; m < B; m++) { a0[m] = 0.f; a1[m] = 0.f; }
#pragma unroll 2
            for (int k = lane; k < HD4; k += 32) {
                float4 x0 = r0[k], x1 = r1[k];
#pragma unroll
                for (int m = 0; m < B; m++) {
                    float4 sv = SM4[m * HD4 + k];
                    float d;
                    d = sv.x - x0.x; a0[m] = fmaf(d, d, a0[m]);
                    d = sv.y - x0.y; a0[m] = fmaf(d, d, a0[m]);
                    d = sv.z - x0.z; a0[m] = fmaf(d, d, a0[m]);
                    d = sv.w - x0.w; a0[m] = fmaf(d, d, a0[m]);
                    d = sv.x - x1.x; a1[m] = fmaf(d, d, a1[m]);
                    d = sv.y - x1.y; a1[m] = fmaf(d, d, a1[m]);
                    d = sv.z - x1.z; a1[m] = fmaf(d, d, a1[m]);
                    d = sv.w - x1.w; a1[m] = fmaf(d, d, a1[m]);
                }
            }
#pragma unroll
            for (int m = 0; m < B; m++) {
                float v0 = a0[m], v1 = a1[m];
#pragma unroll
                for (int off = 16; off; off >>= 1) {
                    v0 += __shfl_down_sync(0xffffffffu, v0, off);
                    v1 += __shfl_down_sync(0xffffffffu, v1, off);
                }
                if (lane == 0) {
                    out[OFF_OP + ((size_t)m * TT + t) * CBN + c0] = -v0;
                    unsigned long long key0 =
                        ((unsigned long long)__float_as_uint(v0) << 32) | (unsigned)c0;
                    atomicMin(&g_amin[m], key0);
                    if (q1) {
                        out[OFF_OP + ((size_t)m * TT + t) * CBN + c1] = -v1;
                        unsigned long long key1 =
                            ((unsigned long long)__float_as_uint(v1) << 32) | (unsigned)c1;
                        atomicMin(&g_amin[m], key1);
                    }
                }
            }
        }
    } else {
        rowdot4<8>(w_k, g_sq2, g_qk2, HD, HD, cid - 118, 30, SM);
    }
}

// slot scores (128 CTAs, 4 prompt rows/warp, float4) + zero ctx/oppre/sq2 (20)
__global__ void k_h(const float* __restrict__ prompt) {
    __shared__ __align__(16) float SM[NS * HD];
    int cid = blockIdx.x, tid = threadIdx.x, w = tid >> 5, lane = tid & 31;
    const float scale = 0.03608439182435161f;
    if (cid < 128) {
        int b = cid >> 4, lc = cid & 15;
        for (int i = tid; i < NS * HD; i += 256) {
            int k = i % HD;
            SM[i] = g_qk2[b * HD + k] + g_sqk2[i];
        }
        __syncthreads();
        const float4* SM4 = reinterpret_cast<const float4*>(SM);
        int l0 = lc * 32 + w * 4;
        const float4* p0 = reinterpret_cast<const float4*>(prompt + ((size_t)(b * LP + l0)) * HD);
        float a0[NS], a1[NS], a2[NS], a3[NS];
#pragma unroll
        for (int s = 0; s < NS; s++) { a0[s] = 0.f; a1[s] = 0.f; a2[s] = 0.f; a3[s] = 0.f; }
#pragma unroll 2
        for (int k = lane; k < HD4; k += 32) {
            float4 v0 = p0[k], v1 = p0[HD4 + k], v2 = p0[2 * HD4 + k], v3 = p0[3 * HD4 + k];
#pragma unroll
            for (int s = 0; s < NS; s++) {
                float4 q = SM4[s * HD4 + k];
                a0[s] = fmaf(v0.x, q.x, a0[s]); a0[s] = fmaf(v0.y, q.y, a0[s]);
                a0[s] = fmaf(v0.z, q.z, a0[s]); a0[s] = fmaf(v0.w, q.w, a0[s]);
                a1[s] = fmaf(v1.x, q.x, a1[s]); a1[s] = fmaf(v1.y, q.y, a1[s]);
                a1[s] = fmaf(v1.z, q.z, a1[s]); a1[s] = fmaf(v1.w, q.w, a1[s]);
                a2[s] = fmaf(v2.x, q.x, a2[s]); a2[s] = fmaf(v2.y, q.y, a2[s]);
                a2[s] = fmaf(v2.z, q.z, a2[s]); a2[s] = fmaf(v2.w, q.w, a2[s]);
                a3[s] = fmaf(v3.x, q.x, a3[s]); a3[s] = fmaf(v3.y, q.y, a3[s]);
                a3[s] = fmaf(v3.z, q.z, a3[s]); a3[s] = fmaf(v3.w, q.w, a3[s]);
            }
        }
#pragma unroll
        for (int s = 0; s < NS; s++) {
            float v0 = a0[s], v1 = a1[s], v2 = a2[s], v3 = a3[s];
#pragma unroll
            for (int off = 16; off; off >>= 1) {
                v0 += __shfl_down_sync(0xffffffffu, v0, off);
                v1 += __shfl_down_sync(0xffffffffu, v1, off);
                v2 += __shfl_down_sync(0xffffffffu, v2, off);
                v3 += __shfl_down_sync(0xffffffffu, v3, off);
            }
            if (lane == 0) {
                float* dst = &g_sscore[(size_t)(b * NS + s) * LP + l0];
                dst[0] = v0 * scale;
                dst[1] = v1 * scale;
                dst[2] = v2 * scale;
                dst[3] = v3 * scale;
            }
        }
    } else {
        for (int i = (cid - 128) * 256 + tid; i < 3 * B * HD; i += 20 * 256) {
            if (i < B * HD) g_ctx[i] = 0.f;
            else if (i < 2 * B * HD) g_oppre[i - B * HD] = 0.f;
            else g_sq2[i - 2 * B * HD] = 0.f;
        }
    }
}

__global__ void k_i(const float* __restrict__ b_gate) {
    __shared__ float SM[NS * LP];
    __shared__ float SRED[32];
    int b = blockIdx.x, tid = threadIdx.x, w = tid >> 5, lane = tid & 31;
    float bg = b_gate[0];
    for (int i = tid; i < NS * LP; i += 256) SM[i] = g_sscore[(size_t)b * NS * LP + i];
    int myge = 0;
    if (tid < B * NS) {
        float lg = g_glog[tid / NS] + g_gq[tid % NS] + bg;
        myge = (lg >= 0.f) ? 1 : 0;
    }
    int any = __syncthreads_or(myge);
    if (tid == 0) {
        float cnt = 0.f;
        if (any) {
            for (int s = 0; s < NS; s++) {
                float lg = g_glog[b] + g_gq[s] + bg;
                float m = (lg >= 0.f) ? 1.f : 0.f;
                SRED[s] = m; cnt += m;
            }
        } else {
            int arg = 0; float best = g_glog[b] + g_gq[0] + bg;
            for (int s = 1; s < NS; s++) {
                float v = g_glog[b] + g_gq[s] + bg;
                if (v > best) { best = v; arg = s; }
            }
            for (int s = 0; s < NS; s++) SRED[s] = (s == arg) ? 1.f : 0.f;
            cnt = 1.f;
        }
        SRED[9] = 1.f / fmaxf(cnt, 1.f);
    }
    __syncthreads();
    float invcnt = SRED[9];
    float wa0 = 0.f, wa1 = 0.f;
    for (int s = 0; s < NS; s++) {
        float v0 = SM[s * LP + tid], v1 = SM[s * LP + tid + 256];
        float mx = fmaxf(v0, v1);
#pragma unroll
        for (int off = 16; off; off >>= 1)
            mx = fmaxf(mx, __shfl_xor_sync(0xffffffffu, mx, off));
        if (lane == 0) SRED[10 + w] = mx;
        __syncthreads();
        mx = SRED[10];
#pragma unroll
        for (int q = 1; q < 8; q++) mx = fmaxf(mx, SRED[10 + q]);
        float e0 = expf(v0 - mx), e1 = expf(v1 - mx);
        float sm = e0 + e1;
#pragma unroll
        for (int off = 16; off; off >>= 1) sm += __shfl_xor_sync(0xffffffffu, sm, off);
        __syncthreads();
        if (lane == 0) SRED[18 + w] = sm;
        __syncthreads();
        float tot = 0.f;
#pragma unroll
        for (int q = 0; q < 8; q++) tot += SRED[18 + q];
        float f = SRED[s] * invcnt / tot;
        wa0 = fmaf(e0, f, wa0);
        wa1 = fmaf(e1, f, wa1);
        __syncthreads();
    }
    g_wcomb[b * LP + tid] = wa0;
    g_wcomb[b * LP + tid + 256] = wa1;
}

// grid 64 (8b x 8ls): uslot += wcomb . prompt, float4 over j
__global__ void k_j(const float* __restrict__ prompt) {
    __shared__ float SW[LP];
    int cid = blockIdx.x, tid = threadIdx.x;
    int b = cid >> 3, ls = cid & 7;
    SW[tid] = g_wcomb[b * LP + tid];
    SW[tid + 256] = g_wcomb[b * LP + tid + 256];
    __syncthreads();
    if (tid < HD4) {
        const float4* pr4 = reinterpret_cast<const float4*>(
            prompt + ((size_t)(b * LP + ls * 64)) * HD);
        float4 acc = make_float4(0.f, 0.f, 0.f, 0.f);
#pragma unroll 4
        for (int l = 0; l < 64; l++) {
            float wv = SW[ls * 64 + l];
            float4 p = pr4[(size_t)l * HD4 + tid];
            FMA4(acc, wv, p);
        }
        int j = tid * 4;
        atomicAdd(&g_uslot[b * HD + j],     acc.x);
        atomicAdd(&g_uslot[b * HD + j + 1], acc.y);
        atomicAdd(&g_uslot[b * HD + j + 2], acc.z);
        atomicAdd(&g_uslot[b * HD + j + 3], acc.w);
    }
}

// grid 32: ssum += uslot @ w_v
__global__ void k_k(const float* __restrict__ w_v) {
    __shared__ __align__(16) float SM[8 * 24];
    colgemv4<8>(g_uslot, HD, w_v, g_ssum, HD, 32, blockIdx.x, SM);
}

__global__ void k_l(const float* __restrict__ cbk, const float* __restrict__ w_stop,
                    float* __restrict__ out, int t) {
    __shared__ float SRED[8];
    int cid = blockIdx.x, tid = threadIdx.x, w = tid >> 5, lane = tid & 31;
    if (cid < 8) {
        int b = cid;
        int idx = (int)(g_amin[b] & 0xFFFFFFFFull);
        float sp = 0.f;
        for (int rep = 0; rep < 3; rep++) {
            int j = rep * 256 + tid;
            float ms = tanhf(cbk[(size_t)idx * HD + j] + g_ssum[b * HD + j]);
            g_msum[b * HD + j] = ms;
            out[OFF_SUM + ((size_t)b * TT + t) * HD + j] = ms;
            sp = fmaf(ms, w_stop[HD + j], sp);
        }
#pragma unroll
        for (int off = 16; off; off >>= 1) sp += __shfl_xor_sync(0xffffffffu, sp, off);
        if (lane == 0) SRED[w] = sp;
        __syncthreads();
        if (tid == 0) {
            float tot = 0.f;
#pragma unroll
            for (int q = 0; q < 8; q++) tot += SRED[q];
            atomicAdd(&g_stoplog[b], tot);
        }
    } else {
        int i = (cid - 8) * 256 + tid;
        g_uslot[i] = 0.f;
    }
}

// GRU matvecs: rowdot4 float4
__global__ void k_m1(const float* __restrict__ stOld, const float* __restrict__ w_ih,
                     const float* __restrict__ w_hh) {
    __shared__ __align__(16) float SM[B * HD];
    int cid = blockIdx.x;
    int half = (cid < 74) ? 0 : 1;
    int base = half ? 74 : 0;
    const float* X = half ? stOld : g_msum;
    const float* W = half ? w_hh : w_ih;
    float* Y = half ? g_gh : g_gi;
    rowdot4<8>(W, X, Y, 3 * HD, 3 * HD, cid - base, 74, SM);
}

__global__ void k_m2(const float* __restrict__ stOld, float* __restrict__ stNew,
                     const float* __restrict__ b_ih, const float* __restrict__ b_hh,
                     const float* __restrict__ b_stop, float* __restrict__ out, int t) {
    int cid = blockIdx.x, tid = threadIdx.x;
    if (cid < 8) {
        int b = cid;
        for (int rep = 0; rep < 3; rep++) {
            int j = rep * 256 + tid;
            float ir = g_gi[b * 3 * HD + j] + b_ih[j];
            float iz = g_gi[b * 3 * HD + HD + j] + b_ih[HD + j];
            float in = g_gi[b * 3 * HD + 2 * HD + j] + b_ih[2 * HD + j];
            float hr = g_gh[b * 3 * HD + j] + b_hh[j];
            float hz = g_gh[b * 3 * HD + HD + j] + b_hh[HD + j];
            float hn = g_gh[b * 3 * HD + 2 * HD + j] + b_hh[2 * HD + j];
            float r = 1.f / (1.f + expf(-(ir + hr)));
            float z = 1.f / (1.f + expf(-(iz + hz)));
            float n = tanhf(in + r * hn);
            stNew[b * HD + j] = (1.f - z) * n + z * stOld[b * HD + j];
        }
    } else if (cid == 8) {
        if (tid == 0) {
            float bs = b_stop[0];
            for (int b = 0; b < B; b++) {
                float lg = g_stoplog[b] + bs;
                out[OFF_SL + b * TT + t] = lg;
                out[OFF_SP + b * TT + t] = 1.f / (1.f + expf(-lg));
                g_stoplog[b] = 0.f;
            }
            if (t == TT - 1) {
                for (int b = 0; b < B; b++) {
                    int len = TT;
                    for (int tt = 0; tt < TT; tt++)
                        if (out[OFF_SL + b * TT + tt] >= 0.f) { len = tt + 1; break; }
                    out[OFF_CL + b] = (float)len;
                }
            }
        }
    } else {
        int i = (cid - 9) * 256 + tid;
        g_ssum[i] = 0.f;
    }
}

// ---------------- host ----------------
extern "C" void kernel_launch(void* const* d_in, const int* in_sizes, int n_in,
                              void* d_out, int out_size) {
    const float* logic    = (const float*)d_in[0];
    const float* prompt   = (const float*)d_in[1];
    const float* cbk      = (const float*)d_in[2];
    const float* w_init   = (const float*)d_in[3];
    const float* w_q      = (const float*)d_in[4];
    const float* w_k      = (const float*)d_in[5];
    const float* w_v      = (const float*)d_in[6];
    const float* slot_q   = (const float*)d_in[7];
    const float* w_slot_q = (const float*)d_in[8];
    const float* w_op_pre = (const float*)d_in[9];
    const float* w_gate   = (const float*)d_in[10];
    const float* b_gate   = (const float*)d_in[11];
    const float* w_stop   = (const float*)d_in[12];
    const float* b_stop   = (const float*)d_in[13];
    const float* w_ih     = (const float*)d_in[14];
    const float* w_hh     = (const float*)d_in[15];
    const float* b_ih     = (const float*)d_in[16];
    const float* b_hh     = (const float*)d_in[17];
    float* out = (float*)d_out;

    void* p;
    float *stateA, *stateB;
    cudaGetSymbolAddress(&p, g_stateA); stateA = (float*)p;
    cudaGetSymbolAddress(&p, g_stateB); stateB = (float*)p;

    k_reset<<<28, 256>>>();
    k_pp1<<<12, 256>>>(prompt, logic);
    k_pp2<<<49, 256>>>(w_init, slot_q, w_slot_q, w_gate);
    k_pp3<<<148, 256>>>(w_k);

    for (int t = 0; t < TT; t++) {
        float* stOld = (t & 1) ? stateB : stateA;
        float* stNew = (t & 1) ? stateA : stateB;
        k_a<<<32, 256>>>(stOld, w_q);
        k_b<<<96, 256>>>(w_k);
        k_c<<<148, 256>>>(prompt);
        k_d<<<64, 256>>>(prompt);
        k_e<<<33, 256>>>(w_v);
        k_f<<<90, 256>>>(w_op_pre, w_slot_q, w_gate, w_stop);
        k_g<<<148, 256>>>(cbk, w_k, out, t);
        k_h<<<148, 256>>>(prompt);
        k_i<<<8, 256>>>(b_gate);
        k_j<<<64, 256>>>(prompt);
        k_k<<<32, 256>>>(w_v);
        k_l<<<32, 256>>>(cbk, w_stop, out, t);
        k_m1<<<148, 256>>>(stOld, w_ih, w_hh);
        k_m2<<<33, 256>>>(stOld, stNew, b_ih, b_hh, b_stop, out, t);
    }
}

// round 11
// speedup vs baseline: 4.3501x; 1.1047x over previous
#include <cuda_runtime.h>
#include <math.h>

#define B    8
#define HD   768
#define HD4  192
#define LP   512
#define LL   256
#define CBN  4096
#define NS   9
#define TT   4

#define OFF_SUM 0
#define OFF_SL  24576
#define OFF_SP  24608
#define OFF_OP  24640
#define OFF_CL  155712

// ---------------- device scratch ----------------
__device__ __align__(16) float g_cat[B * 2 * HD];
__device__ __align__(16) float g_stateA[B * HD];
__device__ __align__(16) float g_stateB[B * HD];
__device__ __align__(16) float g_sq[B * HD];
__device__ __align__(16) float g_qprime[B * HD];
__device__ __align__(16) float g_unum[B * HD];     // Σ exp(s)·prompt accumulator
__device__ float g_Dnum[B];                        // Σ exp(s)
__device__ __align__(16) float g_ctx[B * HD];
__device__ __align__(16) float g_oppre[B * HD];
__device__ __align__(16) float g_sq2[B * HD];
__device__ __align__(16) float g_qk2[B * HD];
__device__ __align__(16) float g_sqs[NS * HD];
__device__ __align__(16) float g_sqk2[NS * HD];
__device__ float g_gq[NS];
__device__ float g_glog[B];
__device__ __align__(16) float g_sscore[B * NS * LP];
__device__ __align__(16) float g_uslot[B * HD];
__device__ __align__(16) float g_ssum[B * HD];
__device__ __align__(16) float g_msum[B * HD];
__device__ __align__(16) float g_gi[B * 3 * HD];
__device__ __align__(16) float g_gh[B * 3 * HD];
__device__ float g_stoplog[B];
__device__ unsigned long long g_amin[B];

// ---------------- helpers ----------------

#define FMA4(ACC, A, Bv) \
    ACC.x = fmaf(A, Bv.x, ACC.x); ACC.y = fmaf(A, Bv.y, ACC.y); \
    ACC.z = fmaf(A, Bv.z, ACC.z); ACC.w = fmaf(A, Bv.w, ACC.w);

// Y[m][4t+c] += sum_{k-split} X[m][k] W[k][4t+c]; float4 over j
template <int M>
__device__ __forceinline__ void colgemv4(const float* __restrict__ X, int ldx,
                                         const float* __restrict__ W,
                                         float* __restrict__ Y,
                                         int K, int nks, int cid, float* SM) {
    int kr = K / nks, k0 = cid * kr;
    for (int i = threadIdx.x; i < M * kr; i += 256) {
        int m = i / kr, kk = i - m * kr;
        SM[i] = X[(size_t)m * ldx + k0 + kk];
    }
    __syncthreads();
    if (threadIdx.x < HD4) {
        const float4* W4 = reinterpret_cast<const float4*>(W);
        float4 acc[M];
#pragma unroll
        for (int m = 0; m < M; m++) acc[m] = make_float4(0.f, 0.f, 0.f, 0.f);
#pragma unroll 4
        for (int kk = 0; kk < kr; kk++) {
            float4 wv = W4[(size_t)(k0 + kk) * HD4 + threadIdx.x];
#pragma unroll
            for (int m = 0; m < M; m++) {
                float s = SM[m * kr + kk];
                FMA4(acc[m], s, wv);
            }
        }
        int j = threadIdx.x * 4;
#pragma unroll
        for (int m = 0; m < M; m++) {
            atomicAdd(&Y[(size_t)m * HD + j],     acc[m].x);
            atomicAdd(&Y[(size_t)m * HD + j + 1], acc[m].y);
            atomicAdd(&Y[(size_t)m * HD + j + 2], acc[m].z);
            atomicAdd(&Y[(size_t)m * HD + j + 3], acc[m].w);
        }
    }
}

// Y[m][n] = sum_k W[n][k] Xg[m][k]; float4 over k
template <int M>
__device__ __forceinline__ void rowdot(const float* __restrict__ W,
                                       const float* __restrict__ Xg,
                                       float* __restrict__ Y,
                                       int cid, int nc, float* SM) {
    int tid = threadIdx.x, w = tid >> 5, lane = tid & 31;
    for (int i = tid; i < M * HD; i += 256) SM[i] = Xg[i];
    __syncthreads();
    const float4* SM4 = reinterpret_cast<const float4*>(SM);
    for (int n = cid * 8 + w; n < HD; n += nc * 8) {
        const float4* wr = reinterpret_cast<const float4*>(W + (size_t)n * HD);
        float acc[M];
#pragma unroll
        for (int m = 0; m < M; m++) acc[m] = 0.f;
#pragma unroll
        for (int k = lane; k < HD4; k += 32) {
            float4 wv = wr[k];
#pragma unroll
            for (int m = 0; m < M; m++) {
                float4 s = SM4[m * HD4 + k];
                acc[m] = fmaf(wv.x, s.x, acc[m]);
                acc[m] = fmaf(wv.y, s.y, acc[m]);
                acc[m] = fmaf(wv.z, s.z, acc[m]);
                acc[m] = fmaf(wv.w, s.w, acc[m]);
            }
        }
#pragma unroll
        for (int m = 0; m < M; m++) {
#pragma unroll
            for (int off = 16; off; off >>= 1)
                acc[m] += __shfl_down_sync(0xffffffffu, acc[m], off);
        }
        if (lane == 0) {
#pragma unroll
            for (int m = 0; m < M; m++) Y[(size_t)m * HD + n] = acc[m];
        }
    }
}

// Y[m][n]; 4 concurrent rows per warp, float4 over k
template <int M>
__device__ __forceinline__ void rowdot4(const float* __restrict__ W,
                                        const float* __restrict__ Xg,
                                        float* __restrict__ Y,
                                        int ldy, int Ntot,
                                        int cid, int nc, float* SM) {
    int tid = threadIdx.x, w = tid >> 5, lane = tid & 31;
    for (int i = tid; i < M * HD; i += 256) SM[i] = Xg[i];
    __syncthreads();
    const float4* SM4 = reinterpret_cast<const float4*>(SM);
    int stride = nc * 8;
    for (int n = cid * 8 + w; n < Ntot; n += 4 * stride) {
        int n1 = n + stride, n2 = n + 2 * stride, n3 = n + 3 * stride;
        bool q1 = n1 < Ntot, q2 = n2 < Ntot, q3 = n3 < Ntot;
        const float4* w0 = reinterpret_cast<const float4*>(W + (size_t)n * HD);
        const float4* w1 = reinterpret_cast<const float4*>(W + (size_t)(q1 ? n1 : n) * HD);
        const float4* w2 = reinterpret_cast<const float4*>(W + (size_t)(q2 ? n2 : n) * HD);
        const float4* w3 = reinterpret_cast<const float4*>(W + (size_t)(q3 ? n3 : n) * HD);
        float a0[M], a1[M], a2[M], a3[M];
#pragma unroll
        for (int m = 0; m < M; m++) { a0[m] = 0.f; a1[m] = 0.f; a2[m] = 0.f; a3[m] = 0.f; }
#pragma unroll 2
        for (int k = lane; k < HD4; k += 32) {
            float4 x0 = w0[k], x1 = w1[k], x2 = w2[k], x3 = w3[k];
#pragma unroll
            for (int m = 0; m < M; m++) {
                float4 s = SM4[m * HD4 + k];
                a0[m] = fmaf(x0.x, s.x, a0[m]); a0[m] = fmaf(x0.y, s.y, a0[m]);
                a0[m] = fmaf(x0.z, s.z, a0[m]); a0[m] = fmaf(x0.w, s.w, a0[m]);
                a1[m] = fmaf(x1.x, s.x, a1[m]); a1[m] = fmaf(x1.y, s.y, a1[m]);
                a1[m] = fmaf(x1.z, s.z, a1[m]); a1[m] = fmaf(x1.w, s.w, a1[m]);
                a2[m] = fmaf(x2.x, s.x, a2[m]); a2[m] = fmaf(x2.y, s.y, a2[m]);
                a2[m] = fmaf(x2.z, s.z, a2[m]); a2[m] = fmaf(x2.w, s.w, a2[m]);
                a3[m] = fmaf(x3.x, s.x, a3[m]); a3[m] = fmaf(x3.y, s.y, a3[m]);
                a3[m] = fmaf(x3.z, s.z, a3[m]); a3[m] = fmaf(x3.w, s.w, a3[m]);
            }
        }
#pragma unroll
        for (int m = 0; m < M; m++) {
            float v0 = a0[m], v1 = a1[m], v2 = a2[m], v3 = a3[m];
#pragma unroll
            for (int off = 16; off; off >>= 1) {
                v0 += __shfl_down_sync(0xffffffffu, v0, off);
                v1 += __shfl_down_sync(0xffffffffu, v1, off);
                v2 += __shfl_down_sync(0xffffffffu, v2, off);
                v3 += __shfl_down_sync(0xffffffffu, v3, off);
            }
            if (lane == 0) {
                Y[(size_t)m * ldy + n] = v0;
                if (q1) Y[(size_t)m * ldy + n1] = v1;
                if (q2) Y[(size_t)m * ldy + n2] = v2;
                if (q3) Y[(size_t)m * ldy + n3] = v3;
            }
        }
    }
}

// ---------------- kernels ----------------

__global__ void k_reset() {
    int i = blockIdx.x * 256 + threadIdx.x;
    if (i < B * HD) {
        g_sq[i] = 0.f; g_unum[i] = 0.f; g_ctx[i] = 0.f; g_oppre[i] = 0.f;
        g_sq2[i] = 0.f; g_uslot[i] = 0.f; g_ssum[i] = 0.f;
    }
    if (i < NS * HD) g_sqs[i] = 0.f;
    if (i < B) { g_amin[i] = 0xFFFFFFFFFFFFFFFFull; g_stoplog[i] = 0.f; g_Dnum[i] = 0.f; }
}

__global__ void k_pp1(const float* __restrict__ prompt, const float* __restrict__ logic) {
    int w = threadIdx.x >> 5, lane = threadIdx.x & 31;
    int wt = blockIdx.x * 8 + w;
    if (wt < 48) {
        int b = wt / 6, hc = wt % 6;
        int h4 = hc * 32 + lane;
        const float4* p = reinterpret_cast<const float4*>(prompt + (size_t)b * LP * HD);
        float4 s = make_float4(0.f, 0.f, 0.f, 0.f);
#pragma unroll 8
        for (int l = 0; l < LP; l++) {
            float4 v = p[(size_t)l * HD4 + h4];
            s.x += v.x; s.y += v.y; s.z += v.z; s.w += v.w;
        }
        int h = h4 * 4;
        float inv = 1.f / (float)LP;
        g_cat[b * 2 * HD + h]     = s.x * inv;
        g_cat[b * 2 * HD + h + 1] = s.y * inv;
        g_cat[b * 2 * HD + h + 2] = s.z * inv;
        g_cat[b * 2 * HD + h + 3] = s.w * inv;
    } else {
        int t2 = wt - 48;
        int b = t2 / 6, hc = t2 % 6;
        int h4 = hc * 32 + lane;
        const float4* p = reinterpret_cast<const float4*>(logic + (size_t)b * LL * HD);
        float4 s = make_float4(0.f, 0.f, 0.f, 0.f);
#pragma unroll 8
        for (int l = 0; l < LL; l++) {
            float4 v = p[(size_t)l * HD4 + h4];
            s.x += v.x; s.y += v.y; s.z += v.z; s.w += v.w;
        }
        int h = h4 * 4;
        float inv = 1.f / (float)LL;
        g_cat[b * 2 * HD + HD + h]     = s.x * inv;
        g_cat[b * 2 * HD + HD + h + 1] = s.y * inv;
        g_cat[b * 2 * HD + HD + h + 2] = s.z * inv;
        g_cat[b * 2 * HD + HD + h + 3] = s.w * inv;
    }
}

__global__ void k_pp2(const float* __restrict__ w_init, const float* __restrict__ slot_q,
                      const float* __restrict__ w_slot_q, const float* __restrict__ w_gate) {
    __shared__ __align__(16) float SM[9 * 48];
    int cid = blockIdx.x, w = threadIdx.x >> 5, lane = threadIdx.x & 31;
    if (cid < 32) {
        colgemv4<8>(g_cat, 2 * HD, w_init, g_sq, 2 * HD, 32, cid, SM);
    } else if (cid < 48) {
        colgemv4<9>(slot_q, HD, w_slot_q, g_sqs, HD, 16, cid - 32, SM);
    } else {
        for (int s = w; s < NS; s += 8) {
            float p = 0.f;
            for (int k = lane; k < HD; k += 32)
                p = fmaf(slot_q[s * HD + k], w_gate[k], p);
#pragma unroll
            for (int off = 16; off; off >>= 1) p += __shfl_down_sync(0xffffffffu, p, off);
            if (lane == 0) g_gq[s] = p;
        }
    }
}

__global__ void k_pp3(const float* __restrict__ w_k) {
    __shared__ __align__(16) float SM[NS * HD];
    int cid = blockIdx.x, tid = threadIdx.x;
    if (cid < 8) {
        int b = cid;
        for (int rep = 0; rep < 3; rep++) {
            int j = rep * 256 + tid;
            g_stateA[b * HD + j] = tanhf(g_sq[b * HD + j]);
            g_sq[b * HD + j] = 0.f;
        }
    } else {
        rowdot<9>(w_k, g_sqs, g_sqk2, cid - 8, 140, SM);
    }
}

// grid 106: sq += state@w_q (32) + gh = w_hh@stOld (74)
__global__ void k_a(const float* __restrict__ st, const float* __restrict__ w_q,
                    const float* __restrict__ w_hh) {
    __shared__ __align__(16) float SM[B * HD];
    if (blockIdx.x < 32) colgemv4<8>(st, HD, w_q, g_sq, HD, 32, blockIdx.x, SM);
    else rowdot4<8>(w_hh, st, g_gh, 3 * HD, 3 * HD, blockIdx.x - 32, 74, SM);
}

// grid 96: qprime = w_k @ sq
__global__ void k_b(const float* __restrict__ w_k) {
    __shared__ __align__(16) float SM[8 * HD];
    rowdot<8>(w_k, g_sq, g_qprime, blockIdx.x, 96, SM);
}

// grid 88: fused state scores + exp + weighted prompt accum (64) + zero sq (24)
__global__ void k_cd(const float* __restrict__ prompt) {
    int cid = blockIdx.x, tid = threadIdx.x, w = tid >> 5, lane = tid & 31;
    const float scale = 0.03608439182435161f;
    if (cid < 64) {
        __shared__ __align__(16) float su[4 * HD];
        __shared__ float sD[8];
        int b = cid >> 3, ch = cid & 7;
        const float4* qp4 = reinterpret_cast<const float4*>(g_qprime + b * HD);
        float4 qv[6];
#pragma unroll
        for (int q = 0; q < 6; q++) qv[q] = qp4[q * 32 + lane];
        float4 acc[6];
#pragma unroll
        for (int q = 0; q < 6; q++) acc[q] = make_float4(0.f, 0.f, 0.f, 0.f);
        float Dw = 0.f;
        const float4* pr = reinterpret_cast<const float4*>(
            prompt + ((size_t)(b * LP + ch * 64)) * HD);
        for (int r = 0; r < 8; r++) {
            int l = w * 8 + r;
            const float4* row = pr + (size_t)l * HD4;
            float4 pv[6];
#pragma unroll
            for (int q = 0; q < 6; q++) pv[q] = row[q * 32 + lane];
            float s = 0.f;
#pragma unroll
            for (int q = 0; q < 6; q++) {
                s = fmaf(pv[q].x, qv[q].x, s); s = fmaf(pv[q].y, qv[q].y, s);
                s = fmaf(pv[q].z, qv[q].z, s); s = fmaf(pv[q].w, qv[q].w, s);
            }
#pragma unroll
            for (int off = 16; off; off >>= 1) s += __shfl_xor_sync(0xffffffffu, s, off);
            float e = expf(s * scale);
            Dw += e;
#pragma unroll
            for (int q = 0; q < 6; q++) { FMA4(acc[q], e, pv[q]); }
        }
        float4* su4 = reinterpret_cast<float4*>(su);
        if (w < 4) {
#pragma unroll
            for (int q = 0; q < 6; q++) su4[w * HD4 + q * 32 + lane] = acc[q];
        }
        if (lane == 0) sD[w] = Dw;
        __syncthreads();
        if (w >= 4) {
#pragma unroll
            for (int q = 0; q < 6; q++) {
                float4 t = su4[(w - 4) * HD4 + q * 32 + lane];
                t.x += acc[q].x; t.y += acc[q].y; t.z += acc[q].z; t.w += acc[q].w;
                su4[(w - 4) * HD4 + q * 32 + lane] = t;
            }
        }
        __syncthreads();
        for (int r = 0; r < 3; r++) {
            int j = r * 256 + tid;
            float v = su[j] + su[HD + j] + su[2 * HD + j] + su[3 * HD + j];
            atomicAdd(&g_unum[b * HD + j], v);
        }
        if (tid == 0) {
            float d = sD[0] + sD[1] + sD[2] + sD[3] + sD[4] + sD[5] + sD[6] + sD[7];
            atomicAdd(&g_Dnum[b], d);
        }
    } else {
        int i = (cid - 64) * 256 + tid;
        g_sq[i] = 0.f;
    }
}

// grid 33: ctx += (unum/D) @ w_v (32) + reset amin (1)
__global__ void k_e(const float* __restrict__ w_v) {
    __shared__ __align__(16) float SM[8 * 24];
    if (blockIdx.x < 32) {
        int cid = blockIdx.x;
        int kr = 24, k0 = cid * kr;
        for (int i = threadIdx.x; i < 8 * kr; i += 256) {
            int m = i / kr, kk = i - m * kr;
            SM[i] = g_unum[m * HD + k0 + kk] / g_Dnum[m];
        }
        __syncthreads();
        if (threadIdx.x < HD4) {
            const float4* W4 = reinterpret_cast<const float4*>(w_v);
            float4 acc[8];
#pragma unroll
            for (int m = 0; m < 8; m++) acc[m] = make_float4(0.f, 0.f, 0.f, 0.f);
#pragma unroll 4
            for (int kk = 0; kk < 24; kk++) {
                float4 wv = W4[(size_t)(k0 + kk) * HD4 + threadIdx.x];
#pragma unroll
                for (int m = 0; m < 8; m++) {
                    float s = SM[m * 24 + kk];
                    FMA4(acc[m], s, wv);
                }
            }
            int j = threadIdx.x * 4;
#pragma unroll
            for (int m = 0; m < 8; m++) {
                atomicAdd(&g_ctx[(size_t)m * HD + j],     acc[m].x);
                atomicAdd(&g_ctx[(size_t)m * HD + j + 1], acc[m].y);
                atomicAdd(&g_ctx[(size_t)m * HD + j + 2], acc[m].z);
                atomicAdd(&g_ctx[(size_t)m * HD + j + 3], acc[m].w);
            }
        }
    } else if (threadIdx.x < B) g_amin[threadIdx.x] = 0xFFFFFFFFFFFFFFFFull;
}

// grid 90: oppre (32), sq2 (32), glog (1), stop1 (1), zero unum/Dnum (24)
__global__ void k_f(const float* __restrict__ w_op_pre, const float* __restrict__ w_slot_q,
                    const float* __restrict__ w_gate, const float* __restrict__ w_stop) {
    __shared__ __align__(16) float SM[8 * 24];
    int cid = blockIdx.x, w = threadIdx.x >> 5, lane = threadIdx.x & 31;
    if (cid < 32) colgemv4<8>(g_ctx, HD, w_op_pre, g_oppre, HD, 32, cid, SM);
    else if (cid < 64) colgemv4<8>(g_ctx, HD, w_slot_q, g_sq2, HD, 32, cid - 32, SM);
    else if (cid == 64) {
        int b = w;
        float p = 0.f;
        for (int k = lane; k < HD; k += 32) p = fmaf(g_ctx[b * HD + k], w_gate[k], p);
#pragma unroll
        for (int off = 16; off; off >>= 1) p += __shfl_down_sync(0xffffffffu, p, off);
        if (lane == 0) g_glog[b] = p;
    } else if (cid == 65) {
        int b = w;
        float p = 0.f;
        for (int k = lane; k < HD; k += 32) p = fmaf(g_ctx[b * HD + k], w_stop[k], p);
#pragma unroll
        for (int off = 16; off; off >>= 1) p += __shfl_down_sync(0xffffffffu, p, off);
        if (lane == 0) g_stoplog[b] = p;
    } else {
        int i = (cid - 66) * 256 + threadIdx.x;
        g_unum[i] = 0.f;
        if (cid == 66 && threadIdx.x < B) g_Dnum[threadIdx.x] = 0.f;
    }
}

// grid 148: codebook (118) + qk2 = w_k@sq2 (30)
__global__ void k_g(const float* __restrict__ cbk, const float* __restrict__ w_k,
                    float* __restrict__ out, int t) {
    __shared__ __align__(16) float SM[B * HD];
    int cid = blockIdx.x, tid = threadIdx.x, w = tid >> 5, lane = tid & 31;
    if (cid < 118) {
        for (int i = tid; i < B * HD; i += 256) SM[i] = g_oppre[i];
        __syncthreads();
        const float4* SM4 = reinterpret_cast<const float4*>(SM);
        for (int c0 = cid * 8 + w; c0 < CBN; c0 += 2 * 944) {
            int c1 = c0 + 944;
            bool q1 = c1 < CBN;
            const float4* r0 = reinterpret_cast<const float4*>(cbk + (size_t)c0 * HD);
            const float4* r1 = reinterpret_cast<const float4*>(cbk + (size_t)(q1 ? c1 : c0) * HD);
            float a0[B], a1[B];
#pragma unroll
            for (int m = 0; m < B; m++) { a0[m] = 0.f; a1[m] = 0.f; }
#pragma unroll 2
            for (int k = lane; k < HD4; k += 32) {
                float4 x0 = r0[k], x1 = r1[k];
#pragma unroll
                for (int m = 0; m < B; m++) {
                    float4 sv = SM4[m * HD4 + k];
                    float d;
                    d = sv.x - x0.x; a0[m] = fmaf(d, d, a0[m]);
                    d = sv.y - x0.y; a0[m] = fmaf(d, d, a0[m]);
                    d = sv.z - x0.z; a0[m] = fmaf(d, d, a0[m]);
                    d = sv.w - x0.w; a0[m] = fmaf(d, d, a0[m]);
                    d = sv.x - x1.x; a1[m] = fmaf(d, d, a1[m]);
                    d = sv.y - x1.y; a1[m] = fmaf(d, d, a1[m]);
                    d = sv.z - x1.z; a1[m] = fmaf(d, d, a1[m]);
                    d = sv.w - x1.w; a1[m] = fmaf(d, d, a1[m]);
                }
            }
#pragma unroll
            for (int m = 0; m < B; m++) {
                float v0 = a0[m], v1 = a1[m];
#pragma unroll
                for (int off = 16; off; off >>= 1) {
                    v0 += __shfl_down_sync(0xffffffffu, v0, off);
                    v1 += __shfl_down_sync(0xffffffffu, v1, off);
                }
                if (lane == 0) {
                    out[OFF_OP + ((size_t)m * TT + t) * CBN + c0] = -v0;
                    unsigned long long key0 =
                        ((unsigned long long)__float_as_uint(v0) << 32) | (unsigned)c0;
                    atomicMin(&g_amin[m], key0);
                    if (q1) {
                        out[OFF_OP + ((size_t)m * TT + t) * CBN + c1] = -v1;
                        unsigned long long key1 =
                            ((unsigned long long)__float_as_uint(v1) << 32) | (unsigned)c1;
                        atomicMin(&g_amin[m], key1);
                    }
                }
            }
        }
    } else {
        rowdot4<8>(w_k, g_sq2, g_qk2, HD, HD, cid - 118, 30, SM);
    }
}

// grid 148: slot scores (128) + zero ctx/oppre/sq2 (20)
__global__ void k_h(const float* __restrict__ prompt) {
    __shared__ __align__(16) float SM[NS * HD];
    int cid = blockIdx.x, tid = threadIdx.x, w = tid >> 5, lane = tid & 31;
    const float scale = 0.03608439182435161f;
    if (cid < 128) {
        int b = cid >> 4, lc = cid & 15;
        for (int i = tid; i < NS * HD; i += 256) {
            int k = i % HD;
            SM[i] = g_qk2[b * HD + k] + g_sqk2[i];
        }
        __syncthreads();
        const float4* SM4 = reinterpret_cast<const float4*>(SM);
        int l0 = lc * 32 + w * 4;
        const float4* p0 = reinterpret_cast<const float4*>(prompt + ((size_t)(b * LP + l0)) * HD);
        float a0[NS], a1[NS], a2[NS], a3[NS];
#pragma unroll
        for (int s = 0; s < NS; s++) { a0[s] = 0.f; a1[s] = 0.f; a2[s] = 0.f; a3[s] = 0.f; }
#pragma unroll 2
        for (int k = lane; k < HD4; k += 32) {
            float4 v0 = p0[k], v1 = p0[HD4 + k], v2 = p0[2 * HD4 + k], v3 = p0[3 * HD4 + k];
#pragma unroll
            for (int s = 0; s < NS; s++) {
                float4 q = SM4[s * HD4 + k];
                a0[s] = fmaf(v0.x, q.x, a0[s]); a0[s] = fmaf(v0.y, q.y, a0[s]);
                a0[s] = fmaf(v0.z, q.z, a0[s]); a0[s] = fmaf(v0.w, q.w, a0[s]);
                a1[s] = fmaf(v1.x, q.x, a1[s]); a1[s] = fmaf(v1.y, q.y, a1[s]);
                a1[s] = fmaf(v1.z, q.z, a1[s]); a1[s] = fmaf(v1.w, q.w, a1[s]);
                a2[s] = fmaf(v2.x, q.x, a2[s]); a2[s] = fmaf(v2.y, q.y, a2[s]);
                a2[s] = fmaf(v2.z, q.z, a2[s]); a2[s] = fmaf(v2.w, q.w, a2[s]);
                a3[s] = fmaf(v3.x, q.x, a3[s]); a3[s] = fmaf(v3.y, q.y, a3[s]);
                a3[s] = fmaf(v3.z, q.z, a3[s]); a3[s] = fmaf(v3.w, q.w, a3[s]);
            }
        }
#pragma unroll
        for (int s = 0; s < NS; s++) {
            float v0 = a0[s], v1 = a1[s], v2 = a2[s], v3 = a3[s];
#pragma unroll
            for (int off = 16; off; off >>= 1) {
                v0 += __shfl_down_sync(0xffffffffu, v0, off);
                v1 += __shfl_down_sync(0xffffffffu, v1, off);
                v2 += __shfl_down_sync(0xffffffffu, v2, off);
                v3 += __shfl_down_sync(0xffffffffu, v3, off);
            }
            if (lane == 0) {
                float* dst = &g_sscore[(size_t)(b * NS + s) * LP + l0];
                dst[0] = v0 * scale;
                dst[1] = v1 * scale;
                dst[2] = v2 * scale;
                dst[3] = v3 * scale;
            }
        }
    } else {
        for (int i = (cid - 128) * 256 + tid; i < 3 * B * HD; i += 20 * 256) {
            if (i < B * HD) g_ctx[i] = 0.f;
            else if (i < 2 * B * HD) g_oppre[i - B * HD] = 0.f;
            else g_sq2[i - 2 * B * HD] = 0.f;
        }
    }
}

// grid 64: fused collapse (replicated) + weighted prompt sweep -> uslot
__global__ void k_jp(const float* __restrict__ prompt, const float* __restrict__ b_gate) {
    __shared__ float SS[NS * LP];
    __shared__ __align__(16) float su[4 * HD];
    __shared__ float sred[NS];
    __shared__ float coef[NS];
    __shared__ float wrow[64];
    int cid = blockIdx.x, tid = threadIdx.x, w = tid >> 5, lane = tid & 31;
    int b = cid >> 3, ch = cid & 7;
    for (int i = tid; i < NS * LP; i += 256) SS[i] = expf(g_sscore[(size_t)b * NS * LP + i]);
    __syncthreads();
    // per-slot denominators
    for (int s = w; s < NS; s += 8) {
        float p = 0.f;
        for (int l = lane; l < LP; l += 32) p += SS[s * LP + l];
#pragma unroll
        for (int off = 16; off; off >>= 1) p += __shfl_down_sync(0xffffffffu, p, off);
        if (lane == 0) sred[s] = p;
    }
    __syncthreads();
    if (tid == 0) {
        float bg = b_gate[0];
        bool any = false;
        for (int bb = 0; bb < B; bb++)
            for (int s = 0; s < NS; s++)
                if (g_glog[bb] + g_gq[s] + bg >= 0.f) any = true;
        float mask[NS], cnt = 0.f;
        if (any) {
            for (int s = 0; s < NS; s++) {
                float m = (g_glog[b] + g_gq[s] + bg >= 0.f) ? 1.f : 0.f;
                mask[s] = m; cnt += m;
            }
        } else {
            int arg = 0; float best = g_glog[b] + g_gq[0] + bg;
            for (int s = 1; s < NS; s++) {
                float v = g_glog[b] + g_gq[s] + bg;
                if (v > best) { best = v; arg = s; }
            }
            for (int s = 0; s < NS; s++) mask[s] = (s == arg) ? 1.f : 0.f;
            cnt = 1.f;
        }
        float invcnt = 1.f / fmaxf(cnt, 1.f);
        for (int s = 0; s < NS; s++) coef[s] = mask[s] * invcnt / sred[s];
    }
    __syncthreads();
    if (tid < 64) {
        int l = ch * 64 + tid;
        float ww = 0.f;
#pragma unroll
        for (int s = 0; s < NS; s++) ww = fmaf(coef[s], SS[s * LP + l], ww);
        wrow[tid] = ww;
    }
    __syncthreads();
    // weighted sweep of own 64 rows
    float4 acc[6];
#pragma unroll
    for (int q = 0; q < 6; q++) acc[q] = make_float4(0.f, 0.f, 0.f, 0.f);
    const float4* pr = reinterpret_cast<const float4*>(prompt + ((size_t)(b * LP + ch * 64)) * HD);
    for (int r = 0; r < 8; r++) {
        int l = w * 8 + r;
        float wt = wrow[l];
        const float4* row = pr + (size_t)l * HD4;
#pragma unroll
        for (int q = 0; q < 6; q++) {
            float4 pv = row[q * 32 + lane];
            FMA4(acc[q], wt, pv);
        }
    }
    float4* su4 = reinterpret_cast<float4*>(su);
    if (w < 4) {
#pragma unroll
        for (int q = 0; q < 6; q++) su4[w * HD4 + q * 32 + lane] = acc[q];
    }
    __syncthreads();
    if (w >= 4) {
#pragma unroll
        for (int q = 0; q < 6; q++) {
            float4 t = su4[(w - 4) * HD4 + q * 32 + lane];
            t.x += acc[q].x; t.y += acc[q].y; t.z += acc[q].z; t.w += acc[q].w;
            su4[(w - 4) * HD4 + q * 32 + lane] = t;
        }
    }
    __syncthreads();
    for (int r = 0; r < 3; r++) {
        int j = r * 256 + tid;
        float v = su[j] + su[HD + j] + su[2 * HD + j] + su[3 * HD + j];
        atomicAdd(&g_uslot[b * HD + j], v);
    }
}

// grid 32: ssum += uslot @ w_v
__global__ void k_k(const float* __restrict__ w_v) {
    __shared__ __align__(16) float SM[8 * 24];
    colgemv4<8>(g_uslot, HD, w_v, g_ssum, HD, 32, blockIdx.x, SM);
}

// grid 32: msum/out (8) + stop2 ; zero uslot (24)
__global__ void k_l(const float* __restrict__ cbk, const float* __restrict__ w_stop,
                    float* __restrict__ out, int t) {
    __shared__ float SRED[8];
    int cid = blockIdx.x, tid = threadIdx.x, w = tid >> 5, lane = tid & 31;
    if (cid < 8) {
        int b = cid;
        int idx = (int)(g_amin[b] & 0xFFFFFFFFull);
        float sp = 0.f;
        for (int rep = 0; rep < 3; rep++) {
            int j = rep * 256 + tid;
            float ms = tanhf(cbk[(size_t)idx * HD + j] + g_ssum[b * HD + j]);
            g_msum[b * HD + j] = ms;
            out[OFF_SUM + ((size_t)b * TT + t) * HD + j] = ms;
            sp = fmaf(ms, w_stop[HD + j], sp);
        }
#pragma unroll
        for (int off = 16; off; off >>= 1) sp += __shfl_xor_sync(0xffffffffu, sp, off);
        if (lane == 0) SRED[w] = sp;
        __syncthreads();
        if (tid == 0) {
            float tot = 0.f;
#pragma unroll
            for (int q = 0; q < 8; q++) tot += SRED[q];
            atomicAdd(&g_stoplog[b], tot);
        }
    } else {
        int i = (cid - 8) * 256 + tid;
        g_uslot[i] = 0.f;
    }
}

// grid 74: gi = w_ih @ msum
__global__ void k_m1(const float* __restrict__ w_ih) {
    __shared__ __align__(16) float SM[B * HD];
    rowdot4<8>(w_ih, g_msum, g_gi, 3 * HD, 3 * HD, blockIdx.x, 74, SM);
}

// grid 33: GRU combine (8) + SL/SP/CL (1) + zero ssum (24)
__global__ void k_m2(const float* __restrict__ stOld, float* __restrict__ stNew,
                     const float* __restrict__ b_ih, const float* __restrict__ b_hh,
                     const float* __restrict__ b_stop, float* __restrict__ out, int t) {
    int cid = blockIdx.x, tid = threadIdx.x;
    if (cid < 8) {
        int b = cid;
        for (int rep = 0; rep < 3; rep++) {
            int j = rep * 256 + tid;
            float ir = g_gi[b * 3 * HD + j] + b_ih[j];
            float iz = g_gi[b * 3 * HD + HD + j] + b_ih[HD + j];
            float in = g_gi[b * 3 * HD + 2 * HD + j] + b_ih[2 * HD + j];
            float hr = g_gh[b * 3 * HD + j] + b_hh[j];
            float hz = g_gh[b * 3 * HD + HD + j] + b_hh[HD + j];
            float hn = g_gh[b * 3 * HD + 2 * HD + j] + b_hh[2 * HD + j];
            float r = 1.f / (1.f + expf(-(ir + hr)));
            float z = 1.f / (1.f + expf(-(iz + hz)));
            float n = tanhf(in + r * hn);
            stNew[b * HD + j] = (1.f - z) * n + z * stOld[b * HD + j];
        }
    } else if (cid == 8) {
        if (tid == 0) {
            float bs = b_stop[0];
            for (int b = 0; b < B; b++) {
                float lg = g_stoplog[b] + bs;
                out[OFF_SL + b * TT + t] = lg;
                out[OFF_SP + b * TT + t] = 1.f / (1.f + expf(-lg));
                g_stoplog[b] = 0.f;
            }
            if (t == TT - 1) {
                for (int b = 0; b < B; b++) {
                    int len = TT;
                    for (int tt = 0; tt < TT; tt++)
                        if (out[OFF_SL + b * TT + tt] >= 0.f) { len = tt + 1; break; }
                    out[OFF_CL + b] = (float)len;
                }
            }
        }
    } else {
        int i = (cid - 9) * 256 + tid;
        g_ssum[i] = 0.f;
    }
}

// ---------------- host ----------------
extern "C" void kernel_launch(void* const* d_in, const int* in_sizes, int n_in,
                              void* d_out, int out_size) {
    const float* logic    = (const float*)d_in[0];
    const float* prompt   = (const float*)d_in[1];
    const float* cbk      = (const float*)d_in[2];
    const float* w_init   = (const float*)d_in[3];
    const float* w_q      = (const float*)d_in[4];
    const float* w_k      = (const float*)d_in[5];
    const float* w_v      = (const float*)d_in[6];
    const float* slot_q   = (const float*)d_in[7];
    const float* w_slot_q = (const float*)d_in[8];
    const float* w_op_pre = (const float*)d_in[9];
    const float* w_gate   = (const float*)d_in[10];
    const float* b_gate   = (const float*)d_in[11];
    const float* w_stop   = (const float*)d_in[12];
    const float* b_stop   = (const float*)d_in[13];
    const float* w_ih     = (const float*)d_in[14];
    const float* w_hh     = (const float*)d_in[15];
    const float* b_ih     = (const float*)d_in[16];
    const float* b_hh     = (const float*)d_in[17];
    float* out = (float*)d_out;

    void* p;
    float *stateA, *stateB;
    cudaGetSymbolAddress(&p, g_stateA); stateA = (float*)p;
    cudaGetSymbolAddress(&p, g_stateB); stateB = (float*)p;

    k_reset<<<28, 256>>>();
    k_pp1<<<12, 256>>>(prompt, logic);
    k_pp2<<<49, 256>>>(w_init, slot_q, w_slot_q, w_gate);
    k_pp3<<<148, 256>>>(w_k);

    for (int t = 0; t < TT; t++) {
        float* stOld = (t & 1) ? stateB : stateA;
        float* stNew = (t & 1) ? stateA : stateB;
        k_a<<<106, 256>>>(stOld, w_q, w_hh);
        k_b<<<96, 256>>>(w_k);
        k_cd<<<88, 256>>>(prompt);
        k_e<<<33, 256>>>(w_v);
        k_f<<<90, 256>>>(w_op_pre, w_slot_q, w_gate, w_stop);
        k_g<<<148, 256>>>(cbk, w_k, out, t);
        k_h<<<148, 256>>>(prompt);
        k_jp<<<64, 256>>>(prompt, b_gate);
        k_k<<<32, 256>>>(w_v);
        k_l<<<32, 256>>>(cbk, w_stop, out, t);
        k_m1<<<74, 256>>>(w_ih);
        k_m2<<<33, 256>>>(stOld, stNew, b_ih, b_hh, b_stop, out, t);
    }
}